// round 7
// baseline (speedup 1.0000x reference)
#include <cuda_runtime.h>
#include <math.h>
#include <stdint.h>

#define N0   50000
#define KP1  25000
#define KP2  12500
#define KP3  6250
#define NE   800000
#define CH   256
#define CIN  32
#define PW1  65536
#define PW2  32768
#define PW3  16384

typedef unsigned long long u64;

// ------------------------- scratch (device globals) -------------------------
__device__ int   g_src[NE], g_dst[NE];
__device__ int   g_e1s[NE], g_e1d[NE], g_e2s[NE], g_e2d[NE], g_e3s[NE], g_e3d[NE];
__device__ int   g_es0[NE], g_es1[NE], g_es2[NE], g_es3[NE];
__device__ int   g_rp0[N0+1], g_rp1[KP1+1], g_rp2[KP2+1], g_rp3[KP3+1];
__device__ int   g_cnt0[N0], g_cur0[N0];
__device__ int   g_cnt1[KP1], g_cur1[KP1];
__device__ int   g_cnt2[KP2], g_cur2[KP2];
__device__ int   g_cnt3[KP3], g_cur3[KP3];
__device__ int   g_m1, g_m2, g_m3, g_flag;
__device__ int   g_map1[N0], g_map2[KP1], g_map3[KP2];
__device__ int   g_perm1[KP1], g_perm2[KP2], g_perm3[KP3];
__device__ int   g_bsum[64];
__device__ __align__(128) float g_h0[N0*CH];
__device__ __align__(128) float g_h1[KP1*CH];
__device__ __align__(128) float g_h2[KP2*CH];
__device__ __align__(128) float g_h3[KP3*CH];
__device__ __align__(128) float g_xa[N0*CH];
__device__ __align__(128) float g_xb[KP1*CH];
__device__ __align__(128) float g_agg[N0*CH];
__device__ float g_score[N0];
__device__ u64   g_keys[PW1];

// ------------------------- fp32x2 helpers ------------------------------------
__device__ __forceinline__ u64 splat2(float f) {
    u64 r;
    unsigned u = __float_as_uint(f);
    asm("mov.b64 %0, {%1, %1};" : "=l"(r) : "r"(u));
    return r;
}
__device__ __forceinline__ void fma2(u64& d, u64 a, u64 b) {
    asm("fma.rn.f32x2 %0, %1, %2, %0;" : "+l"(d) : "l"(a), "l"(b));
}
__device__ __forceinline__ void unpack2(u64 v, float& lo, float& hi) {
    unsigned a, b;
    asm("mov.b64 {%0, %1}, %2;" : "=r"(a), "=r"(b) : "l"(v));
    lo = __uint_as_float(a);
    hi = __uint_as_float(b);
}
__device__ __forceinline__ float4 max4(float4 a, float4 b) {
    return make_float4(fmaxf(a.x, b.x), fmaxf(a.y, b.y),
                       fmaxf(a.z, b.z), fmaxf(a.w, b.w));
}

// ------------------------- init + int64/int32 detect (one launch) ------------
__global__ void k_zeroall(const unsigned* __restrict__ w) {
    int i = blockIdx.x * blockDim.x + threadIdx.x;
    if (i < N0)  { g_cnt0[i] = 0; g_cur0[i] = 0; g_map1[i] = -1; }
    if (i < KP1) { g_cnt1[i] = 0; g_cur1[i] = 0; g_map2[i] = -1; }
    if (i < KP2) { g_cnt2[i] = 0; g_cur2[i] = 0; g_map3[i] = -1; }
    if (i < KP3) { g_cnt3[i] = 0; g_cur3[i] = 0; }
    if (i == 0) { g_m1 = 0; g_m2 = 0; g_m3 = 0; }
    if (blockIdx.x == 0) {
        __shared__ int any;
        if (threadIdx.x == 0) any = 0;
        __syncthreads();
        for (int t = threadIdx.x; t < 2048; t += blockDim.x)
            if (w[2*t + 1] != 0u) any = 1;
        __syncthreads();
        if (threadIdx.x == 0) g_flag = (any == 0) ? 1 : 0;
    }
}

// ------------------------- edge decode + level-0 dst count -------------------
__global__ void k_convert(const unsigned* __restrict__ w) {
    int i = blockIdx.x * blockDim.x + threadIdx.x;
    if (i >= NE) return;
    int s, d;
    if (g_flag) {
        s = (int)w[2*i];
        d = (int)w[2*(NE + i)];
    } else {
        const int* p = (const int*)w;
        s = p[i];
        d = p[NE + i];
    }
    g_src[i] = s;
    g_dst[i] = d;
    atomicAdd(&g_cnt0[d], 1);
}

// ------------------------- parallel exclusive scan ---------------------------
__global__ void k_scan_block(const int* __restrict__ in, int* bsum, int n) {
    __shared__ int sh[1024];
    int t = threadIdx.x;
    int base = blockIdx.x * 4096 + t * 4;
    int s = 0;
#pragma unroll
    for (int q = 0; q < 4; q++) {
        int idx = base + q;
        s += (idx < n) ? in[idx] : 0;
    }
    sh[t] = s;
    __syncthreads();
    for (int o = 512; o > 0; o >>= 1) {
        if (t < o) sh[t] += sh[t + o];
        __syncthreads();
    }
    if (t == 0) bsum[blockIdx.x] = sh[0];
}

__global__ void k_scan_down(const int* __restrict__ in, const int* __restrict__ bsum,
                            int* out, int n) {
    __shared__ int sh[1024];
    __shared__ int base0;
    int t = threadIdx.x;
    if (t < 32) {
        int nb = gridDim.x;
        int v = (t < nb) ? bsum[t] : 0;
#pragma unroll
        for (int o = 1; o < 32; o <<= 1) {
            int u = __shfl_up_sync(0xffffffffu, v, o);
            if (t >= o) v += u;
        }
        if (t == 0) base0 = 0;
        __syncwarp();
        if ((int)t == (int)blockIdx.x - 1) base0 = v;
    }
    int base = blockIdx.x * 4096 + t * 4;
    int v4[4];
    int s = 0;
#pragma unroll
    for (int q = 0; q < 4; q++) {
        int idx = base + q;
        v4[q] = (idx < n) ? in[idx] : 0;
        s += v4[q];
    }
    sh[t] = s;
    __syncthreads();
    for (int o = 1; o < 1024; o <<= 1) {
        int u = (t >= o) ? sh[t - o] : 0;
        __syncthreads();
        sh[t] += u;
        __syncthreads();
    }
    int pref = base0 + sh[t] - s;
#pragma unroll
    for (int q = 0; q < 4; q++) {
        int idx = base + q;
        if (idx < n) out[idx] = pref;
        if (idx == n - 1) out[n] = pref + v4[q];
        pref += v4[q];
    }
}

__global__ void k_scatter(const int* __restrict__ s, const int* __restrict__ d,
                          const int* mptr, int fixedM,
                          const int* __restrict__ rp, int* cur, int* esrc) {
    int m = mptr ? *mptr : fixedM;
    int i = blockIdx.x * blockDim.x + threadIdx.x;
    if (i >= m) return;
    int dd = d[i];
    int pos = rp[dd] + atomicAdd(&cur[dd], 1);
    esrc[pos] = s[i];
}

__global__ void k_relabel(const int* __restrict__ ps, const int* __restrict__ pd,
                          const int* mptr, int fixedM,
                          const int* __restrict__ map,
                          int* os, int* od, int* om, int* cnt) {
    int m = mptr ? *mptr : fixedM;
    int i = blockIdx.x * blockDim.x + threadIdx.x;
    if (i >= m) return;
    int a = map[ps[i]], b = map[pd[i]];
    if (a >= 0 && b >= 0) {
        int p = atomicAdd(om, 1);
        os[p] = a; od[p] = b;
        atomicAdd(&cnt[b], 1);
    }
}

// ------------------------- max aggregation (CSR, vectorized) -----------------
__global__ void k_aggmax32(const int* __restrict__ rp, const int* __restrict__ es,
                           const float* __restrict__ x, float* agg, int n) {
    int warp = (blockIdx.x * blockDim.x + threadIdx.x) >> 5;
    int lane = threadIdx.x & 31;
    if (warp >= n) return;
    int s = rp[warp], e = rp[warp + 1];
    float m = -INFINITY;
    int t = s;
    for (; t + 4 <= e; t += 4) {
        float v0 = x[(size_t)es[t] * CIN + lane];
        float v1 = x[(size_t)es[t+1] * CIN + lane];
        float v2 = x[(size_t)es[t+2] * CIN + lane];
        float v3 = x[(size_t)es[t+3] * CIN + lane];
        m = fmaxf(m, fmaxf(fmaxf(v0, v1), fmaxf(v2, v3)));
    }
    for (; t < e; t++)
        m = fmaxf(m, x[(size_t)es[t] * CIN + lane]);
    agg[(size_t)warp * CIN + lane] = (e > s) ? m : 0.0f;
}

__global__ void k_aggmax256(const int* __restrict__ rp, const int* __restrict__ es,
                            const float* __restrict__ x, float* agg, int n) {
    int warp = (blockIdx.x * blockDim.x + threadIdx.x) >> 5;
    int lane = threadIdx.x & 31;
    if (warp >= n) return;
    int s = rp[warp], e = rp[warp + 1];
    const float ninf = -INFINITY;
    float4 m0 = make_float4(ninf, ninf, ninf, ninf);
    float4 m1 = m0;
    int t = s;
    for (; t + 2 <= e; t += 2) {
        const float4* p0 = (const float4*)(x + (size_t)es[t] * CH) + lane * 2;
        const float4* p1 = (const float4*)(x + (size_t)es[t+1] * CH) + lane * 2;
        float4 a0 = p0[0], a1 = p0[1];
        float4 b0 = p1[0], b1 = p1[1];
        m0 = max4(m0, a0); m1 = max4(m1, a1);
        m0 = max4(m0, b0); m1 = max4(m1, b1);
    }
    if (t < e) {
        const float4* p0 = (const float4*)(x + (size_t)es[t] * CH) + lane * 2;
        m0 = max4(m0, p0[0]); m1 = max4(m1, p0[1]);
    }
    float4 z = make_float4(0.f, 0.f, 0.f, 0.f);
    bool has = (e > s);
    float4* ar = (float4*)(agg + (size_t)warp * CH) + lane * 2;
    ar[0] = has ? m0 : z;
    ar[1] = has ? m1 : z;
}

// ------------------------- fused dual GEMM (FFMA2, BM=64, dbuf) --------------
// C[n,256] = relu?( A0[n,Ka]@B0 + A1[n,Ka]@B1 + bias )
// BM=64, BN=128, BK=16, 256 threads, 4x8 micro-tile, double buffered.
__global__ void __launch_bounds__(256, 3)
k_gemm2(const float* __restrict__ A0, const float* __restrict__ A1, int Ka,
        const float* __restrict__ B0, const float* __restrict__ B1,
        const float* __restrict__ bias, float* __restrict__ C,
        int n, int relu) {
    __shared__ __align__(16) float As[2][16][64];
    __shared__ __align__(16) float Bs[2][16][128];
    const int bm = blockIdx.x * 64, bn = blockIdx.y * 128;
    const int tid = threadIdx.x;
    const int tx = tid & 15, ty = tid >> 4;
    const int m0 = ty * 4, c0 = tx * 8;

    u64 acc[2][8];
#pragma unroll
    for (int i = 0; i < 2; i++)
#pragma unroll
        for (int j = 0; j < 8; j++) acc[i][j] = 0ull;

    const int aRow = tid >> 2;          // 0..63
    const int aK   = (tid & 3) * 4;     // 0,4,8,12
    const int bRow = tid >> 4;          // 0..15
    const int bCol = (tid & 15) * 8;
    const int Ktot = 2 * Ka;
    const int nk = Ktot / 16;

    float4 av, bv0, bv1;

    // prologue: tile 0 -> buffer 0
    {
        av = make_float4(0.f, 0.f, 0.f, 0.f);
        if (bm + aRow < n)
            av = *(const float4*)(A0 + (size_t)(bm + aRow) * Ka + aK);
        const float* bp = B0 + (size_t)bRow * CH + bn + bCol;
        bv0 = *(const float4*)bp;
        bv1 = *(const float4*)(bp + 4);
        As[0][aK + 0][aRow] = av.x; As[0][aK + 1][aRow] = av.y;
        As[0][aK + 2][aRow] = av.z; As[0][aK + 3][aRow] = av.w;
        *(float4*)(&Bs[0][bRow][bCol])     = bv0;
        *(float4*)(&Bs[0][bRow][bCol + 4]) = bv1;
    }
    __syncthreads();

    for (int it = 0; it < nk; it++) {
        const int buf = it & 1;
        const bool more = (it + 1 < nk);
        if (more) {
            int k0 = (it + 1) * 16;
            const int h = (k0 >= Ka);
            const int kl = k0 - (h ? Ka : 0);
            const float* A = h ? A1 : A0;
            const float* B = h ? B1 : B0;
            av = make_float4(0.f, 0.f, 0.f, 0.f);
            if (bm + aRow < n)
                av = *(const float4*)(A + (size_t)(bm + aRow) * Ka + kl + aK);
            const float* bp = B + (size_t)(kl + bRow) * CH + bn + bCol;
            bv0 = *(const float4*)bp;
            bv1 = *(const float4*)(bp + 4);
        }

#pragma unroll
        for (int kk = 0; kk < 16; kk++) {
            const u64* ap64 = (const u64*)(&As[buf][kk][m0]);
            u64 a0 = ap64[0], a1 = ap64[1];
            float4 bx = *(const float4*)(&Bs[buf][kk][c0]);
            float4 by = *(const float4*)(&Bs[buf][kk][c0 + 4]);
            u64 b0s = splat2(bx.x), b1s = splat2(bx.y);
            u64 b2s = splat2(bx.z), b3s = splat2(bx.w);
            u64 b4s = splat2(by.x), b5s = splat2(by.y);
            u64 b6s = splat2(by.z), b7s = splat2(by.w);
            fma2(acc[0][0], a0, b0s); fma2(acc[0][1], a0, b1s);
            fma2(acc[0][2], a0, b2s); fma2(acc[0][3], a0, b3s);
            fma2(acc[0][4], a0, b4s); fma2(acc[0][5], a0, b5s);
            fma2(acc[0][6], a0, b6s); fma2(acc[0][7], a0, b7s);
            fma2(acc[1][0], a1, b0s); fma2(acc[1][1], a1, b1s);
            fma2(acc[1][2], a1, b2s); fma2(acc[1][3], a1, b3s);
            fma2(acc[1][4], a1, b4s); fma2(acc[1][5], a1, b5s);
            fma2(acc[1][6], a1, b6s); fma2(acc[1][7], a1, b7s);
        }

        if (more) {
            const int nb = buf ^ 1;
            As[nb][aK + 0][aRow] = av.x; As[nb][aK + 1][aRow] = av.y;
            As[nb][aK + 2][aRow] = av.z; As[nb][aK + 3][aRow] = av.w;
            *(float4*)(&Bs[nb][bRow][bCol])     = bv0;
            *(float4*)(&Bs[nb][bRow][bCol + 4]) = bv1;
        }
        __syncthreads();
    }

    float bv[8];
#pragma unroll
    for (int j = 0; j < 8; j++) bv[j] = bias[bn + c0 + j];

#pragma unroll
    for (int p = 0; p < 2; p++) {
        int r0 = bm + m0 + 2 * p;
        float v0[8], v1[8];
#pragma unroll
        for (int j = 0; j < 8; j++) {
            float lo, hi;
            unpack2(acc[p][j], lo, hi);
            v0[j] = lo + bv[j];
            v1[j] = hi + bv[j];
            if (relu) { v0[j] = fmaxf(v0[j], 0.f); v1[j] = fmaxf(v1[j], 0.f); }
        }
        if (r0 < n) {
            float* cp = C + (size_t)r0 * CH + bn + c0;
            *(float4*)cp       = make_float4(v0[0], v0[1], v0[2], v0[3]);
            *(float4*)(cp + 4) = make_float4(v0[4], v0[5], v0[6], v0[7]);
        }
        if (r0 + 1 < n) {
            float* cp = C + (size_t)(r0 + 1) * CH + bn + c0;
            *(float4*)cp       = make_float4(v1[0], v1[1], v1[2], v1[3]);
            *(float4*)(cp + 4) = make_float4(v1[4], v1[5], v1[6], v1[7]);
        }
    }
}

// ------------------------- TopK pooling --------------------------------------
__global__ void k_scorekey(const float* __restrict__ x, const float* __restrict__ w,
                           float* score, u64* keys, int n, int P) {
    int gw = (blockIdx.x * blockDim.x + threadIdx.x) >> 5;
    int lane = threadIdx.x & 31;
    if (gw >= P) return;
    if (gw >= n) {
        if (lane == 0) keys[gw] = 0xFFFFFFFFFFFFFFFFull;
        return;
    }
    float p = 0.f, w2 = 0.f;
    const float* xr = x + (size_t)gw * CH;
    for (int c = lane; c < CH; c += 32) {
        float wv = w[c];
        p += xr[c] * wv;
        w2 += wv * wv;
    }
#pragma unroll
    for (int o = 16; o > 0; o >>= 1) {
        p  += __shfl_xor_sync(0xffffffffu, p, o);
        w2 += __shfl_xor_sync(0xffffffffu, w2, o);
    }
    if (lane == 0) {
        float s = tanhf(p / sqrtf(w2));
        score[gw] = s;
        unsigned u = __float_as_uint(s);
        unsigned mono = (u & 0x80000000u) ? ~u : (u | 0x80000000u);
        keys[gw] = ((u64)(~mono) << 32) | (unsigned)gw;
    }
}

__global__ void k_bit_full8(u64* keys) {
    extern __shared__ u64 s[];
    int base = blockIdx.x * 8192;
    int t = threadIdx.x;
#pragma unroll
    for (int i = 0; i < 8; i++) s[t + i * 1024] = keys[base + t + i * 1024];
    __syncthreads();
    for (int k = 2; k <= 8192; k <<= 1) {
        for (int j = k >> 1; j > 0; j >>= 1) {
#pragma unroll
            for (int q = 0; q < 4; q++) {
                int p = t + q * 1024;
                int li = ((p & ~(j - 1)) << 1) | (p & (j - 1));
                bool up = (((base + li) & k) == 0);
                u64 a = s[li], b = s[li + j];
                if ((a > b) == up) { s[li] = b; s[li + j] = a; }
            }
            __syncthreads();
        }
    }
#pragma unroll
    for (int i = 0; i < 8; i++) keys[base + t + i * 1024] = s[t + i * 1024];
}

__global__ void k_bit_smem8(u64* keys, int k) {
    extern __shared__ u64 s[];
    int base = blockIdx.x * 8192;
    int t = threadIdx.x;
#pragma unroll
    for (int i = 0; i < 8; i++) s[t + i * 1024] = keys[base + t + i * 1024];
    __syncthreads();
    for (int j = 4096; j > 0; j >>= 1) {
#pragma unroll
        for (int q = 0; q < 4; q++) {
            int p = t + q * 1024;
            int li = ((p & ~(j - 1)) << 1) | (p & (j - 1));
            bool up = (((base + li) & k) == 0);
            u64 a = s[li], b = s[li + j];
            if ((a > b) == up) { s[li] = b; s[li + j] = a; }
        }
        __syncthreads();
    }
#pragma unroll
    for (int i = 0; i < 8; i++) keys[base + t + i * 1024] = s[t + i * 1024];
}

__global__ void k_bit_glob(u64* keys, int j, int k) {
    int i = blockIdx.x * blockDim.x + threadIdx.x;
    int ixj = i ^ j;
    if (ixj > i) {
        bool up = ((i & k) == 0);
        u64 a = keys[i], b = keys[ixj];
        if ((a > b) == up) { keys[i] = b; keys[ixj] = a; }
    }
}

__global__ void k_bit_glob2(u64* keys, int j, int k) {
    int t = blockIdx.x * blockDim.x + threadIdx.x;
    int j2 = j >> 1;
    int b = ((t & ~(j2 - 1)) << 1) | (t & (j2 - 1));
    b = ((b & ~(j - 1)) << 1) | (b & (j - 1));
    u64 v0 = keys[b], v1 = keys[b + j2], v2 = keys[b + j], v3 = keys[b + j + j2];
    bool up = ((b & k) == 0);
    u64 tmp;
    if ((v0 > v2) == up) { tmp = v0; v0 = v2; v2 = tmp; }
    if ((v1 > v3) == up) { tmp = v1; v1 = v3; v3 = tmp; }
    if ((v0 > v1) == up) { tmp = v0; v0 = v1; v1 = tmp; }
    if ((v2 > v3) == up) { tmp = v2; v2 = v3; v3 = tmp; }
    keys[b] = v0; keys[b + j2] = v1; keys[b + j] = v2; keys[b + j + j2] = v3;
}

__global__ void k_build(const u64* __restrict__ keys, const float* __restrict__ xin,
                        const float* __restrict__ score, float* xout,
                        int* perm, int* map, int k) {
    int gw = (blockIdx.x * blockDim.x + threadIdx.x) >> 5;
    int lane = threadIdx.x & 31;
    if (gw >= k) return;
    int idx = (int)(keys[gw] & 0xFFFFFFFFull);
    if (lane == 0) { perm[gw] = idx; map[idx] = gw; }
    float v = score[idx];
    const float4* xr = (const float4*)(xin + (size_t)idx * CH);
    float4* xo = (float4*)(xout + (size_t)gw * CH);
#pragma unroll
    for (int c = lane; c < 64; c += 32) {
        float4 a = xr[c];
        xo[c] = make_float4(a.x * v, a.y * v, a.z * v, a.w * v);
    }
}

// ------------------------- unpool: xa = h + gather(deep via map) -------------
__global__ void k_unpool(const float* __restrict__ h, const float* __restrict__ deep,
                         const int* __restrict__ map, float* __restrict__ xa, int n) {
    int i = blockIdx.x * blockDim.x + threadIdx.x;
    if (i >= n * 64) return;
    int r = i >> 6, c4 = i & 63;
    float4 v = ((const float4*)h)[i];
    int g = map[r];
    if (g >= 0) {
        float4 d = ((const float4*)deep)[g * 64 + c4];
        v.x += d.x; v.y += d.y; v.z += d.z; v.w += d.w;
    }
    ((float4*)xa)[i] = v;
}

// ------------------------- final conv (M=3) + tanh*0.5 -----------------------
__global__ void k_final(const float* __restrict__ agg, const float* __restrict__ x,
                        const float* __restrict__ wl, const float* __restrict__ wr,
                        const float* __restrict__ b, float* out, int n) {
    __shared__ float swl[CH * 3], swr[CH * 3], sb[3];
    for (int i = threadIdx.x; i < CH * 3; i += blockDim.x) {
        swl[i] = wl[i];
        swr[i] = wr[i];
    }
    if (threadIdx.x < 3) sb[threadIdx.x] = b[threadIdx.x];
    __syncthreads();
    int node = blockIdx.x * blockDim.x + threadIdx.x;
    if (node >= n) return;
    float a0 = sb[0], a1 = sb[1], a2 = sb[2];
    const float4* ar = (const float4*)(agg + (size_t)node * CH);
    const float4* xr = (const float4*)(x + (size_t)node * CH);
#pragma unroll 2
    for (int c4 = 0; c4 < 64; c4++) {
        float4 av = ar[c4], xv = xr[c4];
        int c = c4 * 4;
        a0 += av.x * swl[c * 3 + 0] + xv.x * swr[c * 3 + 0];
        a1 += av.x * swl[c * 3 + 1] + xv.x * swr[c * 3 + 1];
        a2 += av.x * swl[c * 3 + 2] + xv.x * swr[c * 3 + 2];
        a0 += av.y * swl[c * 3 + 3] + xv.y * swr[c * 3 + 3];
        a1 += av.y * swl[c * 3 + 4] + xv.y * swr[c * 3 + 4];
        a2 += av.y * swl[c * 3 + 5] + xv.y * swr[c * 3 + 5];
        a0 += av.z * swl[c * 3 + 6] + xv.z * swr[c * 3 + 6];
        a1 += av.z * swl[c * 3 + 7] + xv.z * swr[c * 3 + 7];
        a2 += av.z * swl[c * 3 + 8] + xv.z * swr[c * 3 + 8];
        a0 += av.w * swl[c * 3 + 9] + xv.w * swr[c * 3 + 9];
        a1 += av.w * swl[c * 3 + 10] + xv.w * swr[c * 3 + 10];
        a2 += av.w * swl[c * 3 + 11] + xv.w * swr[c * 3 + 11];
    }
    out[node * 3 + 0] = tanhf(a0) * 0.5f;
    out[node * 3 + 1] = tanhf(a1) * 0.5f;
    out[node * 3 + 2] = tanhf(a2) * 0.5f;
}

// ------------------------- host orchestration --------------------------------
static inline int cdiv(int a, int b) { return (a + b - 1) / b; }

template <class T>
static void* gp(const T& sym) {
    void* p = nullptr;
    cudaGetSymbolAddress(&p, sym);
    return p;
}

extern "C" void kernel_launch(void* const* d_in, const int* in_sizes, int n_in,
                              void* d_out, int out_size) {
    const float* x_in = (const float*)d_in[0];
    const unsigned* eidx = (const unsigned*)d_in[1];
    const float* w0l  = (const float*)d_in[2];
    const float* w0r  = (const float*)d_in[3];
    const float* b0   = (const float*)d_in[4];
    const float* dwl  = (const float*)d_in[5];
    const float* dwr  = (const float*)d_in[6];
    const float* db   = (const float*)d_in[7];
    const float* poolw = (const float*)d_in[8];
    const float* uwl  = (const float*)d_in[9];
    const float* uwr  = (const float*)d_in[10];
    const float* ub   = (const float*)d_in[11];
    const float* uwlL = (const float*)d_in[12];
    const float* uwrL = (const float*)d_in[13];
    const float* ubL  = (const float*)d_in[14];
    float* out = (float*)d_out;

    static bool attr_done = false;
    if (!attr_done) {
        cudaFuncSetAttribute(k_bit_full8, cudaFuncAttributeMaxDynamicSharedMemorySize, 65536);
        cudaFuncSetAttribute(k_bit_smem8, cudaFuncAttributeMaxDynamicSharedMemorySize, 65536);
        attr_done = true;
    }

    int* srcP = (int*)gp(g_src);
    int* dstP = (int*)gp(g_dst);
    int* e1sP = (int*)gp(g_e1s); int* e1dP = (int*)gp(g_e1d);
    int* e2sP = (int*)gp(g_e2s); int* e2dP = (int*)gp(g_e2d);
    int* e3sP = (int*)gp(g_e3s); int* e3dP = (int*)gp(g_e3d);
    int* es0P = (int*)gp(g_es0); int* es1P = (int*)gp(g_es1);
    int* es2P = (int*)gp(g_es2); int* es3P = (int*)gp(g_es3);
    int* rp0P = (int*)gp(g_rp0); int* rp1P = (int*)gp(g_rp1);
    int* rp2P = (int*)gp(g_rp2); int* rp3P = (int*)gp(g_rp3);
    int* cnt0P = (int*)gp(g_cnt0); int* cur0P = (int*)gp(g_cur0);
    int* cnt1P = (int*)gp(g_cnt1); int* cur1P = (int*)gp(g_cur1);
    int* cnt2P = (int*)gp(g_cnt2); int* cur2P = (int*)gp(g_cur2);
    int* cnt3P = (int*)gp(g_cnt3); int* cur3P = (int*)gp(g_cur3);
    int* m1P = (int*)gp(g_m1); int* m2P = (int*)gp(g_m2); int* m3P = (int*)gp(g_m3);
    int* map1P = (int*)gp(g_map1); int* map2P = (int*)gp(g_map2); int* map3P = (int*)gp(g_map3);
    int* p1P = (int*)gp(g_perm1); int* p2P = (int*)gp(g_perm2); int* p3P = (int*)gp(g_perm3);
    int* bsumP = (int*)gp(g_bsum);
    float* h0P = (float*)gp(g_h0);
    float* h1P = (float*)gp(g_h1);
    float* h2P = (float*)gp(g_h2);
    float* h3P = (float*)gp(g_h3);
    float* xaP = (float*)gp(g_xa);
    float* xbP = (float*)gp(g_xb);
    float* aggP = (float*)gp(g_agg);
    float* scoreP = (float*)gp(g_score);
    u64* keysP = (u64*)gp(g_keys);

    const int EG = cdiv(NE, 256);

    auto scan = [&](const int* in, int* outp, int n) {
        int nb = cdiv(n, 4096);
        k_scan_block<<<nb, 1024>>>(in, bsumP, n);
        k_scan_down<<<nb, 1024>>>(in, bsumP, outp, n);
    };

    auto conv = [&](const float* xin, int n, const int* rp, const int* esrc,
                    const float* wl, const float* wr, const float* bias,
                    float* outb, int relu) {
        k_aggmax256<<<cdiv(n, 8), 256>>>(rp, esrc, xin, aggP, n);
        dim3 g(cdiv(n, 64), 2);
        k_gemm2<<<g, 256>>>(aggP, xin, CH, wl, wr, bias, outb, n, relu);
    };

    auto pool = [&](const float* xin, int n, int P, int k, const float* w,
                    int* perm, int* map, float* xout) {
        k_scorekey<<<cdiv(P * 32, 256), 256>>>(xin, w, scoreP, keysP, n, P);
        k_bit_full8<<<P / 8192, 1024, 65536>>>(keysP);
        for (int kk = 16384; kk <= P; kk <<= 1) {
            int j = kk >> 1;
            while (j >= 8192) {
                if (j >= 16384) {
                    k_bit_glob2<<<P / 4 / 256, 256>>>(keysP, j, kk);
                    j >>= 2;
                } else {
                    k_bit_glob<<<P / 256, 256>>>(keysP, j, kk);
                    j >>= 1;
                }
            }
            k_bit_smem8<<<P / 8192, 1024, 65536>>>(keysP, kk);
        }
        k_build<<<cdiv(k * 32, 256), 256>>>(keysP, xin, scoreP, xout, perm, map, k);
    };

    // init + decode + level-0 CSR
    k_zeroall<<<cdiv(N0, 256), 256>>>(eidx);
    k_convert<<<EG, 256>>>(eidx);
    scan(cnt0P, rp0P, N0);
    k_scatter<<<EG, 256>>>(srcP, dstP, nullptr, NE, rp0P, cur0P, es0P);

    // level-0 conv (C_IN=32)
    k_aggmax32<<<cdiv(N0, 8), 256>>>(rp0P, es0P, x_in, aggP, N0);
    {
        dim3 g(cdiv(N0, 64), 2);
        k_gemm2<<<g, 256>>>(aggP, x_in, CIN, w0l, w0r, b0, h0P, N0, 1);
    }

    // --- pool 1 + conv 1 ---
    pool(h0P, N0, PW1, KP1, poolw, p1P, map1P, xaP);
    k_relabel<<<EG, 256>>>(srcP, dstP, nullptr, NE, map1P, e1sP, e1dP, m1P, cnt1P);
    scan(cnt1P, rp1P, KP1);
    k_scatter<<<EG, 256>>>(e1sP, e1dP, m1P, 0, rp1P, cur1P, es1P);
    conv(xaP, KP1, rp1P, es1P, dwl, dwr, db, h1P, 1);

    // --- pool 2 + conv 2 ---
    pool(h1P, KP1, PW2, KP2, poolw + CH, p2P, map2P, xaP);
    k_relabel<<<EG, 256>>>(e1sP, e1dP, m1P, 0, map2P, e2sP, e2dP, m2P, cnt2P);
    scan(cnt2P, rp2P, KP2);
    k_scatter<<<EG, 256>>>(e2sP, e2dP, m2P, 0, rp2P, cur2P, es2P);
    conv(xaP, KP2, rp2P, es2P, dwl + CH*CH, dwr + CH*CH, db + CH, h2P, 1);

    // --- pool 3 + conv 3 ---
    pool(h2P, KP2, PW3, KP3, poolw + 2*CH, p3P, map3P, xaP);
    k_relabel<<<EG, 256>>>(e2sP, e2dP, m2P, 0, map3P, e3sP, e3dP, m3P, cnt3P);
    scan(cnt3P, rp3P, KP3);
    k_scatter<<<EG, 256>>>(e3sP, e3dP, m3P, 0, rp3P, cur3P, es3P);
    conv(xaP, KP3, rp3P, es3P, dwl + 2*CH*CH, dwr + 2*CH*CH, db + 2*CH, h3P, 1);

    // --- up path (gather-based unpool) ---
    k_unpool<<<cdiv(KP2 * 64, 256), 256>>>(h2P, h3P, map3P, xaP, KP2);
    conv(xaP, KP2, rp2P, es2P, uwl, uwr, ub, xbP, 1);

    k_unpool<<<cdiv(KP1 * 64, 256), 256>>>(h1P, xbP, map2P, xaP, KP1);
    conv(xaP, KP1, rp1P, es1P, uwl + CH*CH, uwr + CH*CH, ub + CH, xbP, 1);

    k_unpool<<<cdiv(N0 * 64, 256), 256>>>(h0P, xbP, map1P, xaP, N0);
    k_aggmax256<<<cdiv(N0, 8), 256>>>(rp0P, es0P, xaP, aggP, N0);
    k_final<<<cdiv(N0, 256), 256>>>(aggP, xaP, uwlL, uwrL, ubL, out, N0);
}

// round 9
// speedup vs baseline: 1.0864x; 1.0864x over previous
#include <cuda_runtime.h>
#include <math.h>
#include <stdint.h>

#define N0   50000
#define KP1  25000
#define KP2  12500
#define KP3  6250
#define NE   800000
#define CH   256
#define CIN  32
#define PW1  65536
#define PW2  32768
#define PW3  16384

typedef unsigned long long u64;

// ------------------------- scratch (device globals) -------------------------
__device__ int   g_src[NE], g_dst[NE];
__device__ int   g_e1s[NE], g_e1d[NE], g_e2s[NE], g_e2d[NE], g_e3s[NE], g_e3d[NE];
__device__ int   g_es0[NE], g_es1[NE], g_es2[NE], g_es3[NE];
__device__ int   g_rp0[N0+1], g_rp1[KP1+1], g_rp2[KP2+1], g_rp3[KP3+1];
__device__ int   g_cnt0[N0], g_cur0[N0];
__device__ int   g_cnt1[KP1], g_cur1[KP1];
__device__ int   g_cnt2[KP2], g_cur2[KP2];
__device__ int   g_cnt3[KP3], g_cur3[KP3];
__device__ int   g_m1, g_m2, g_m3, g_flag;
__device__ int   g_map1[N0], g_map2[KP1], g_map3[KP2];
__device__ int   g_perm1[KP1], g_perm2[KP2], g_perm3[KP3];
__device__ int   g_bsum[64];
__device__ __align__(128) float g_h0[N0*CH];
__device__ __align__(128) float g_h1[KP1*CH];
__device__ __align__(128) float g_h2[KP2*CH];
__device__ __align__(128) float g_h3[KP3*CH];
__device__ __align__(128) float g_xa[N0*CH];
__device__ __align__(128) float g_xb[KP1*CH];
__device__ __align__(128) float g_agg[N0*CH];
__device__ float g_score[N0];
__device__ u64   g_keys[PW1];
// tf32-split planes (fp32 storage, mantissa pre-truncated via cvt.rna.tf32)
__device__ __align__(128) float g_atf[2ull * N0 * 512];       // A: 2 planes
__device__ __align__(128) float g_w0tf[2 * 256 * 64];         // conv0 B planes
__device__ __align__(128) float g_wctf[5 * 2 * 256 * 512];    // 5 big-conv B planes

// ------------------------- helpers ------------------------------------------
__device__ __forceinline__ float4 max4(float4 a, float4 b) {
    return make_float4(fmaxf(a.x, b.x), fmaxf(a.y, b.y),
                       fmaxf(a.z, b.z), fmaxf(a.w, b.w));
}

__device__ __forceinline__ void tsplit(float v, float& hi, float& lo) {
    unsigned u;
    asm("cvt.rna.tf32.f32 %0, %1;" : "=r"(u) : "f"(v));
    hi = __uint_as_float(u);
    float r = v - hi;
    asm("cvt.rna.tf32.f32 %0, %1;" : "=r"(u) : "f"(r));
    lo = __uint_as_float(u);
}

#define MMA_TF32(d, a, b)                                                  \
    asm volatile(                                                          \
        "mma.sync.aligned.m16n8k8.row.col.f32.tf32.tf32.f32 "              \
        "{%0,%1,%2,%3}, {%4,%5,%6,%7}, {%8,%9}, {%0,%1,%2,%3};"            \
        : "+f"((d)[0]), "+f"((d)[1]), "+f"((d)[2]), "+f"((d)[3])           \
        : "r"((a)[0]), "r"((a)[1]), "r"((a)[2]), "r"((a)[3]),              \
          "r"((b)[0]), "r"((b)[1]))

// ------------------------- init + int64/int32 detect -------------------------
__global__ void k_zeroall(const unsigned* __restrict__ w) {
    int i = blockIdx.x * blockDim.x + threadIdx.x;
    if (i < N0)  { g_cnt0[i] = 0; g_cur0[i] = 0; g_map1[i] = -1; }
    if (i < KP1) { g_cnt1[i] = 0; g_cur1[i] = 0; g_map2[i] = -1; }
    if (i < KP2) { g_cnt2[i] = 0; g_cur2[i] = 0; g_map3[i] = -1; }
    if (i < KP3) { g_cnt3[i] = 0; g_cur3[i] = 0; }
    if (i == 0) { g_m1 = 0; g_m2 = 0; g_m3 = 0; }
    if (blockIdx.x == 0) {
        __shared__ int any;
        if (threadIdx.x == 0) any = 0;
        __syncthreads();
        for (int t = threadIdx.x; t < 2048; t += blockDim.x)
            if (w[2*t + 1] != 0u) any = 1;
        __syncthreads();
        if (threadIdx.x == 0) g_flag = (any == 0) ? 1 : 0;
    }
}

// ------------------------- weight split to tf32 planes -----------------------
__global__ void k_wsplit(const float* __restrict__ w0l, const float* __restrict__ w0r,
                         const float* __restrict__ dwl, const float* __restrict__ dwr,
                         const float* __restrict__ uwl, const float* __restrict__ uwr) {
    int i = blockIdx.x * blockDim.x + threadIdx.x;
    if (i < 16384) {  // conv0: B[n(256)][k(64)], k<32 -> w0l[k][n], else w0r
        int nn = i >> 6, k = i & 63;
        float v = (k < 32) ? w0l[k * 256 + nn] : w0r[(k - 32) * 256 + nn];
        float hi, lo;
        tsplit(v, hi, lo);
        g_w0tf[i] = hi;
        g_w0tf[16384 + i] = lo;
        return;
    }
    int t = i - 16384;
    if (t >= 5 * 131072) return;
    int c = t / 131072;            // conv 0..4 (down0..2, up0..1)
    int r = t - c * 131072;
    int nn = r >> 9, k = r & 511;
    float v;
    if (k < 256) v = (c < 3) ? dwl[c * 65536 + k * 256 + nn]
                             : uwl[(c - 3) * 65536 + k * 256 + nn];
    else {
        int kk = k - 256;
        v = (c < 3) ? dwr[c * 65536 + kk * 256 + nn]
                    : uwr[(c - 3) * 65536 + kk * 256 + nn];
    }
    float hi, lo;
    tsplit(v, hi, lo);
    size_t base = (size_t)c * 262144 + r;
    g_wctf[base] = hi;
    g_wctf[base + 131072] = lo;
}

// ------------------------- A split: [agg|xin] -> 2 tf32 planes ---------------
__global__ void k_asplit(const float* __restrict__ agg, const float* __restrict__ xin,
                         float* __restrict__ gA, int n, int Ka, int sh) {
    int j = blockIdx.x * blockDim.x + threadIdx.x;   // group of 4 elems
    int K2 = 2 * Ka;
    int total = (n << sh) >> 2;
    if (j >= total) return;
    int i = j << 2;
    int row = i >> sh;
    int col = i & (K2 - 1);
    const float* srcp = (col < Ka) ? (agg + (size_t)row * Ka + col)
                                   : (xin + (size_t)row * Ka + (col - Ka));
    float4 v = *(const float4*)srcp;
    float4 h, l;
    tsplit(v.x, h.x, l.x);
    tsplit(v.y, h.y, l.y);
    tsplit(v.z, h.z, l.z);
    tsplit(v.w, h.w, l.w);
    size_t stride = ((size_t)n << sh);
    *(float4*)(gA + i) = h;
    *(float4*)(gA + stride + i) = l;
}

// ------------------------- edge decode + level-0 dst count -------------------
__global__ void k_convert(const unsigned* __restrict__ w) {
    int i = blockIdx.x * blockDim.x + threadIdx.x;
    if (i >= NE) return;
    int s, d;
    if (g_flag) {
        s = (int)w[2*i];
        d = (int)w[2*(NE + i)];
    } else {
        const int* p = (const int*)w;
        s = p[i];
        d = p[NE + i];
    }
    g_src[i] = s;
    g_dst[i] = d;
    atomicAdd(&g_cnt0[d], 1);
}

// ------------------------- parallel exclusive scan ---------------------------
__global__ void k_scan_block(const int* __restrict__ in, int* bsum, int n) {
    __shared__ int sh[1024];
    int t = threadIdx.x;
    int base = blockIdx.x * 4096 + t * 4;
    int s = 0;
#pragma unroll
    for (int q = 0; q < 4; q++) {
        int idx = base + q;
        s += (idx < n) ? in[idx] : 0;
    }
    sh[t] = s;
    __syncthreads();
    for (int o = 512; o > 0; o >>= 1) {
        if (t < o) sh[t] += sh[t + o];
        __syncthreads();
    }
    if (t == 0) bsum[blockIdx.x] = sh[0];
}

__global__ void k_scan_down(const int* __restrict__ in, const int* __restrict__ bsum,
                            int* out, int n) {
    __shared__ int sh[1024];
    __shared__ int base0;
    int t = threadIdx.x;
    if (t < 32) {
        int nb = gridDim.x;
        int v = (t < nb) ? bsum[t] : 0;
#pragma unroll
        for (int o = 1; o < 32; o <<= 1) {
            int u = __shfl_up_sync(0xffffffffu, v, o);
            if (t >= o) v += u;
        }
        if (t == 0) base0 = 0;
        __syncwarp();
        if ((int)t == (int)blockIdx.x - 1) base0 = v;
    }
    int base = blockIdx.x * 4096 + t * 4;
    int v4[4];
    int s = 0;
#pragma unroll
    for (int q = 0; q < 4; q++) {
        int idx = base + q;
        v4[q] = (idx < n) ? in[idx] : 0;
        s += v4[q];
    }
    sh[t] = s;
    __syncthreads();
    for (int o = 1; o < 1024; o <<= 1) {
        int u = (t >= o) ? sh[t - o] : 0;
        __syncthreads();
        sh[t] += u;
        __syncthreads();
    }
    int pref = base0 + sh[t] - s;
#pragma unroll
    for (int q = 0; q < 4; q++) {
        int idx = base + q;
        if (idx < n) out[idx] = pref;
        if (idx == n - 1) out[n] = pref + v4[q];
        pref += v4[q];
    }
}

__global__ void k_scatter(const int* __restrict__ s, const int* __restrict__ d,
                          const int* mptr, int fixedM,
                          const int* __restrict__ rp, int* cur, int* esrc) {
    int m = mptr ? *mptr : fixedM;
    int i = blockIdx.x * blockDim.x + threadIdx.x;
    if (i >= m) return;
    int dd = d[i];
    int pos = rp[dd] + atomicAdd(&cur[dd], 1);
    esrc[pos] = s[i];
}

__global__ void k_relabel(const int* __restrict__ ps, const int* __restrict__ pd,
                          const int* mptr, int fixedM,
                          const int* __restrict__ map,
                          int* os, int* od, int* om, int* cnt) {
    int m = mptr ? *mptr : fixedM;
    int i = blockIdx.x * blockDim.x + threadIdx.x;
    if (i >= m) return;
    int a = map[ps[i]], b = map[pd[i]];
    if (a >= 0 && b >= 0) {
        int p = atomicAdd(om, 1);
        os[p] = a; od[p] = b;
        atomicAdd(&cnt[b], 1);
    }
}

// ------------------------- max aggregation (CSR) -----------------------------
__global__ void k_aggmax32(const int* __restrict__ rp, const int* __restrict__ es,
                           const float* __restrict__ x, float* agg, int n) {
    int warp = (blockIdx.x * blockDim.x + threadIdx.x) >> 5;
    int lane = threadIdx.x & 31;
    if (warp >= n) return;
    int s = rp[warp], e = rp[warp + 1];
    float m = -INFINITY;
    int t = s;
    for (; t + 4 <= e; t += 4) {
        float v0 = x[(size_t)es[t] * CIN + lane];
        float v1 = x[(size_t)es[t+1] * CIN + lane];
        float v2 = x[(size_t)es[t+2] * CIN + lane];
        float v3 = x[(size_t)es[t+3] * CIN + lane];
        m = fmaxf(m, fmaxf(fmaxf(v0, v1), fmaxf(v2, v3)));
    }
    for (; t < e; t++)
        m = fmaxf(m, x[(size_t)es[t] * CIN + lane]);
    agg[(size_t)warp * CIN + lane] = (e > s) ? m : 0.0f;
}

__global__ void k_aggmax256(const int* __restrict__ rp, const int* __restrict__ es,
                            const float* __restrict__ x, float* agg, int n) {
    int warp = (blockIdx.x * blockDim.x + threadIdx.x) >> 5;
    int lane = threadIdx.x & 31;
    if (warp >= n) return;
    int s = rp[warp], e = rp[warp + 1];
    const float ninf = -INFINITY;
    float4 m0 = make_float4(ninf, ninf, ninf, ninf);
    float4 m1 = m0;
    int t = s;
    for (; t + 2 <= e; t += 2) {
        const float4* p0 = (const float4*)(x + (size_t)es[t] * CH) + lane * 2;
        const float4* p1 = (const float4*)(x + (size_t)es[t+1] * CH) + lane * 2;
        float4 a0 = p0[0], a1 = p0[1];
        float4 b0 = p1[0], b1 = p1[1];
        m0 = max4(m0, a0); m1 = max4(m1, a1);
        m0 = max4(m0, b0); m1 = max4(m1, b1);
    }
    if (t < e) {
        const float4* p0 = (const float4*)(x + (size_t)es[t] * CH) + lane * 2;
        m0 = max4(m0, p0[0]); m1 = max4(m1, p0[1]);
    }
    float4 z = make_float4(0.f, 0.f, 0.f, 0.f);
    bool has = (e > s);
    float4* ar = (float4*)(agg + (size_t)warp * CH) + lane * 2;
    ar[0] = has ? m0 : z;
    ar[1] = has ? m1 : z;
}

// ------------------------- 3xTF32 tensor GEMM (mma.sync) ---------------------
// C[n,256] = relu( A[n,Ktot] @ B(256,Ktot)^T + bias ), A/B as 2 tf32 planes.
// Block: 128x128 tile (grid.y=2), 256 thr = 8 warps (warp grid 4m x 2n),
// warp tile 32x64, BK=32. smem stride 136 floats (conflict-free fragments).
#define SAW  136
#define SPL  (32 * SAW)          // one plane-chunk: 32 k-rows
#define MG_SMEM (4 * SPL * 4)    // 2 planes A + 2 planes B, bytes = 69632

__global__ void __launch_bounds__(256, 2)
k_mgemm(const float* __restrict__ gA, const float* __restrict__ gB,
        const float* __restrict__ bias, float* __restrict__ C,
        int n, int Ktot, int planeB) {
    extern __shared__ float sm[];
    float* sA = sm;              // [2][32][SAW]
    float* sB = sm + 2 * SPL;    // [2][32][SAW]
    const int tid = threadIdx.x;
    const int wid = tid >> 5, lane = tid & 31;
    const int wm = wid & 3, wn = wid >> 2;
    const int g = lane >> 2, t4 = lane & 3;
    const int bm = blockIdx.x * 128, bn = blockIdx.y * 128;
    const size_t planeA = (size_t)n * Ktot;
    const int nc = Ktot >> 5;

    float acc[2][8][4];
#pragma unroll
    for (int mt = 0; mt < 2; mt++)
#pragma unroll
        for (int nt = 0; nt < 8; nt++)
#pragma unroll
            for (int q = 0; q < 4; q++) acc[mt][nt][q] = 0.f;

    const int lr = tid >> 1;            // 0..127
    const int lk = (tid & 1) * 16;      // 0 or 16
    const int arow = bm + lr;
    const bool aok = arow < n;

    for (int c = 0; c < nc; c++) {
#pragma unroll
        for (int p = 0; p < 2; p++) {
            const float4* As4 = (const float4*)(gA + p * planeA +
                                                (size_t)arow * Ktot + c * 32 + lk);
            const float4* Bs4 = (const float4*)(gB + (size_t)p * planeB +
                                                (size_t)(bn + lr) * Ktot + c * 32 + lk);
            float* pa = sA + p * SPL;
            float* pb = sB + p * SPL;
#pragma unroll
            for (int i = 0; i < 4; i++) {
                float4 va = aok ? As4[i] : make_float4(0.f, 0.f, 0.f, 0.f);
                float4 vb = Bs4[i];
                int k = lk + i * 4;
                pa[(k + 0) * SAW + lr] = va.x;
                pa[(k + 1) * SAW + lr] = va.y;
                pa[(k + 2) * SAW + lr] = va.z;
                pa[(k + 3) * SAW + lr] = va.w;
                pb[(k + 0) * SAW + lr] = vb.x;
                pb[(k + 1) * SAW + lr] = vb.y;
                pb[(k + 2) * SAW + lr] = vb.z;
                pb[(k + 3) * SAW + lr] = vb.w;
            }
        }
        __syncthreads();

#pragma unroll
        for (int k8 = 0; k8 < 4; k8++) {
            const int kb = k8 * 8;
            unsigned a[2][2][4];
#pragma unroll
            for (int p = 0; p < 2; p++) {
                const float* pa = sA + p * SPL;
#pragma unroll
                for (int mt = 0; mt < 2; mt++) {
                    int m0 = wm * 32 + mt * 16;
                    a[p][mt][0] = __float_as_uint(pa[(kb + t4) * SAW + m0 + g]);
                    a[p][mt][1] = __float_as_uint(pa[(kb + t4) * SAW + m0 + g + 8]);
                    a[p][mt][2] = __float_as_uint(pa[(kb + t4 + 4) * SAW + m0 + g]);
                    a[p][mt][3] = __float_as_uint(pa[(kb + t4 + 4) * SAW + m0 + g + 8]);
                }
            }
#pragma unroll
            for (int nt = 0; nt < 8; nt++) {
                int n0 = wn * 64 + nt * 8;
                unsigned b0[2], b1[2];
                b0[0] = __float_as_uint(sB[(kb + t4) * SAW + n0 + g]);
                b0[1] = __float_as_uint(sB[(kb + t4 + 4) * SAW + n0 + g]);
                b1[0] = __float_as_uint(sB[SPL + (kb + t4) * SAW + n0 + g]);
                b1[1] = __float_as_uint(sB[SPL + (kb + t4 + 4) * SAW + n0 + g]);
#pragma unroll
                for (int mt = 0; mt < 2; mt++) {
                    MMA_TF32(acc[mt][nt], a[0][mt], b0);   // A0*B0
                    MMA_TF32(acc[mt][nt], a[0][mt], b1);   // A0*B1
                    MMA_TF32(acc[mt][nt], a[1][mt], b0);   // A1*B0
                }
            }
        }
        __syncthreads();
    }

    // epilogue: bias + relu, direct global stores (float2 per row-pair)
#pragma unroll
    for (int mt = 0; mt < 2; mt++) {
        int r0 = bm + wm * 32 + mt * 16 + g;
#pragma unroll
        for (int nt = 0; nt < 8; nt++) {
            int col = bn + wn * 64 + nt * 8 + t4 * 2;
            float bb0 = bias[col], bb1 = bias[col + 1];
            if (r0 < n) {
                float2 v;
                v.x = fmaxf(acc[mt][nt][0] + bb0, 0.f);
                v.y = fmaxf(acc[mt][nt][1] + bb1, 0.f);
                *(float2*)(C + (size_t)r0 * CH + col) = v;
            }
            if (r0 + 8 < n) {
                float2 v;
                v.x = fmaxf(acc[mt][nt][2] + bb0, 0.f);
                v.y = fmaxf(acc[mt][nt][3] + bb1, 0.f);
                *(float2*)(C + (size_t)(r0 + 8) * CH + col) = v;
            }
        }
    }
}

// ------------------------- TopK pooling --------------------------------------
__global__ void k_scorekey(const float* __restrict__ x, const float* __restrict__ w,
                           float* score, u64* keys, int n, int P) {
    int gw = (blockIdx.x * blockDim.x + threadIdx.x) >> 5;
    int lane = threadIdx.x & 31;
    if (gw >= P) return;
    if (gw >= n) {
        if (lane == 0) keys[gw] = 0xFFFFFFFFFFFFFFFFull;
        return;
    }
    float p = 0.f, w2 = 0.f;
    const float* xr = x + (size_t)gw * CH;
    for (int c = lane; c < CH; c += 32) {
        float wv = w[c];
        p += xr[c] * wv;
        w2 += wv * wv;
    }
#pragma unroll
    for (int o = 16; o > 0; o >>= 1) {
        p  += __shfl_xor_sync(0xffffffffu, p, o);
        w2 += __shfl_xor_sync(0xffffffffu, w2, o);
    }
    if (lane == 0) {
        float s = tanhf(p / sqrtf(w2));
        score[gw] = s;
        unsigned u = __float_as_uint(s);
        unsigned mono = (u & 0x80000000u) ? ~u : (u | 0x80000000u);
        keys[gw] = ((u64)(~mono) << 32) | (unsigned)gw;
    }
}

__global__ void k_bit_full8(u64* keys) {
    extern __shared__ u64 s[];
    int base = blockIdx.x * 8192;
    int t = threadIdx.x;
#pragma unroll
    for (int i = 0; i < 8; i++) s[t + i * 1024] = keys[base + t + i * 1024];
    __syncthreads();
    for (int k = 2; k <= 8192; k <<= 1) {
        for (int j = k >> 1; j > 0; j >>= 1) {
#pragma unroll
            for (int q = 0; q < 4; q++) {
                int p = t + q * 1024;
                int li = ((p & ~(j - 1)) << 1) | (p & (j - 1));
                bool up = (((base + li) & k) == 0);
                u64 a = s[li], b = s[li + j];
                if ((a > b) == up) { s[li] = b; s[li + j] = a; }
            }
            __syncthreads();
        }
    }
#pragma unroll
    for (int i = 0; i < 8; i++) keys[base + t + i * 1024] = s[t + i * 1024];
}

__global__ void k_bit_smem8(u64* keys, int k) {
    extern __shared__ u64 s[];
    int base = blockIdx.x * 8192;
    int t = threadIdx.x;
#pragma unroll
    for (int i = 0; i < 8; i++) s[t + i * 1024] = keys[base + t + i * 1024];
    __syncthreads();
    for (int j = 4096; j > 0; j >>= 1) {
#pragma unroll
        for (int q = 0; q < 4; q++) {
            int p = t + q * 1024;
            int li = ((p & ~(j - 1)) << 1) | (p & (j - 1));
            bool up = (((base + li) & k) == 0);
            u64 a = s[li], b = s[li + j];
            if ((a > b) == up) { s[li] = b; s[li + j] = a; }
        }
        __syncthreads();
    }
#pragma unroll
    for (int i = 0; i < 8; i++) keys[base + t + i * 1024] = s[t + i * 1024];
}

__global__ void k_bit_glob(u64* keys, int j, int k) {
    int i = blockIdx.x * blockDim.x + threadIdx.x;
    int ixj = i ^ j;
    if (ixj > i) {
        bool up = ((i & k) == 0);
        u64 a = keys[i], b = keys[ixj];
        if ((a > b) == up) { keys[i] = b; keys[ixj] = a; }
    }
}

__global__ void k_bit_glob2(u64* keys, int j, int k) {
    int t = blockIdx.x * blockDim.x + threadIdx.x;
    int j2 = j >> 1;
    int b = ((t & ~(j2 - 1)) << 1) | (t & (j2 - 1));
    b = ((b & ~(j - 1)) << 1) | (b & (j - 1));
    u64 v0 = keys[b], v1 = keys[b + j2], v2 = keys[b + j], v3 = keys[b + j + j2];
    bool up = ((b & k) == 0);
    u64 tmp;
    if ((v0 > v2) == up) { tmp = v0; v0 = v2; v2 = tmp; }
    if ((v1 > v3) == up) { tmp = v1; v1 = v3; v3 = tmp; }
    if ((v0 > v1) == up) { tmp = v0; v0 = v1; v1 = tmp; }
    if ((v2 > v3) == up) { tmp = v2; v2 = v3; v3 = tmp; }
    keys[b] = v0; keys[b + j2] = v1; keys[b + j] = v2; keys[b + j + j2] = v3;
}

__global__ void k_build(const u64* __restrict__ keys, const float* __restrict__ xin,
                        const float* __restrict__ score, float* xout,
                        int* perm, int* map, int k) {
    int gw = (blockIdx.x * blockDim.x + threadIdx.x) >> 5;
    int lane = threadIdx.x & 31;
    if (gw >= k) return;
    int idx = (int)(keys[gw] & 0xFFFFFFFFull);
    if (lane == 0) { perm[gw] = idx; map[idx] = gw; }
    float v = score[idx];
    const float4* xr = (const float4*)(xin + (size_t)idx * CH);
    float4* xo = (float4*)(xout + (size_t)gw * CH);
#pragma unroll
    for (int c = lane; c < 64; c += 32) {
        float4 a = xr[c];
        xo[c] = make_float4(a.x * v, a.y * v, a.z * v, a.w * v);
    }
}

// ------------------------- unpool --------------------------------------------
__global__ void k_unpool(const float* __restrict__ h, const float* __restrict__ deep,
                         const int* __restrict__ map, float* __restrict__ xa, int n) {
    int i = blockIdx.x * blockDim.x + threadIdx.x;
    if (i >= n * 64) return;
    int r = i >> 6, c4 = i & 63;
    float4 v = ((const float4*)h)[i];
    int g = map[r];
    if (g >= 0) {
        float4 d = ((const float4*)deep)[g * 64 + c4];
        v.x += d.x; v.y += d.y; v.z += d.z; v.w += d.w;
    }
    ((float4*)xa)[i] = v;
}

// ------------------------- final conv (M=3) + tanh*0.5 -----------------------
__global__ void k_final(const float* __restrict__ agg, const float* __restrict__ x,
                        const float* __restrict__ wl, const float* __restrict__ wr,
                        const float* __restrict__ b, float* out, int n) {
    __shared__ float swl[CH * 3], swr[CH * 3], sb[3];
    for (int i = threadIdx.x; i < CH * 3; i += blockDim.x) {
        swl[i] = wl[i];
        swr[i] = wr[i];
    }
    if (threadIdx.x < 3) sb[threadIdx.x] = b[threadIdx.x];
    __syncthreads();
    int node = blockIdx.x * blockDim.x + threadIdx.x;
    if (node >= n) return;
    float a0 = sb[0], a1 = sb[1], a2 = sb[2];
    const float4* ar = (const float4*)(agg + (size_t)node * CH);
    const float4* xr = (const float4*)(x + (size_t)node * CH);
#pragma unroll 2
    for (int c4 = 0; c4 < 64; c4++) {
        float4 av = ar[c4], xv = xr[c4];
        int c = c4 * 4;
        a0 += av.x * swl[c * 3 + 0] + xv.x * swr[c * 3 + 0];
        a1 += av.x * swl[c * 3 + 1] + xv.x * swr[c * 3 + 1];
        a2 += av.x * swl[c * 3 + 2] + xv.x * swr[c * 3 + 2];
        a0 += av.y * swl[c * 3 + 3] + xv.y * swr[c * 3 + 3];
        a1 += av.y * swl[c * 3 + 4] + xv.y * swr[c * 3 + 4];
        a2 += av.y * swl[c * 3 + 5] + xv.y * swr[c * 3 + 5];
        a0 += av.z * swl[c * 3 + 6] + xv.z * swr[c * 3 + 6];
        a1 += av.z * swl[c * 3 + 7] + xv.z * swr[c * 3 + 7];
        a2 += av.z * swl[c * 3 + 8] + xv.z * swr[c * 3 + 8];
        a0 += av.w * swl[c * 3 + 9] + xv.w * swr[c * 3 + 9];
        a1 += av.w * swl[c * 3 + 10] + xv.w * swr[c * 3 + 10];
        a2 += av.w * swl[c * 3 + 11] + xv.w * swr[c * 3 + 11];
    }
    out[node * 3 + 0] = tanhf(a0) * 0.5f;
    out[node * 3 + 1] = tanhf(a1) * 0.5f;
    out[node * 3 + 2] = tanhf(a2) * 0.5f;
}

// ------------------------- host orchestration --------------------------------
static inline int cdiv(int a, int b) { return (a + b - 1) / b; }

template <class T>
static void* gp(const T& sym) {
    void* p = nullptr;
    cudaGetSymbolAddress(&p, sym);
    return p;
}

extern "C" void kernel_launch(void* const* d_in, const int* in_sizes, int n_in,
                              void* d_out, int out_size) {
    const float* x_in = (const float*)d_in[0];
    const unsigned* eidx = (const unsigned*)d_in[1];
    const float* w0l  = (const float*)d_in[2];
    const float* w0r  = (const float*)d_in[3];
    const float* b0   = (const float*)d_in[4];
    const float* dwl  = (const float*)d_in[5];
    const float* dwr  = (const float*)d_in[6];
    const float* db   = (const float*)d_in[7];
    const float* poolw = (const float*)d_in[8];
    const float* uwl  = (const float*)d_in[9];
    const float* uwr  = (const float*)d_in[10];
    const float* ub   = (const float*)d_in[11];
    const float* uwlL = (const float*)d_in[12];
    const float* uwrL = (const float*)d_in[13];
    const float* ubL  = (const float*)d_in[14];
    float* out = (float*)d_out;

    static bool attr_done = false;
    if (!attr_done) {
        cudaFuncSetAttribute(k_bit_full8, cudaFuncAttributeMaxDynamicSharedMemorySize, 65536);
        cudaFuncSetAttribute(k_bit_smem8, cudaFuncAttributeMaxDynamicSharedMemorySize, 65536);
        cudaFuncSetAttribute(k_mgemm, cudaFuncAttributeMaxDynamicSharedMemorySize, MG_SMEM);
        attr_done = true;
    }

    int* srcP = (int*)gp(g_src);
    int* dstP = (int*)gp(g_dst);
    int* e1sP = (int*)gp(g_e1s); int* e1dP = (int*)gp(g_e1d);
    int* e2sP = (int*)gp(g_e2s); int* e2dP = (int*)gp(g_e2d);
    int* e3sP = (int*)gp(g_e3s); int* e3dP = (int*)gp(g_e3d);
    int* es0P = (int*)gp(g_es0); int* es1P = (int*)gp(g_es1);
    int* es2P = (int*)gp(g_es2); int* es3P = (int*)gp(g_es3);
    int* rp0P = (int*)gp(g_rp0); int* rp1P = (int*)gp(g_rp1);
    int* rp2P = (int*)gp(g_rp2); int* rp3P = (int*)gp(g_rp3);
    int* cnt0P = (int*)gp(g_cnt0); int* cur0P = (int*)gp(g_cur0);
    int* cnt1P = (int*)gp(g_cnt1); int* cur1P = (int*)gp(g_cur1);
    int* cnt2P = (int*)gp(g_cnt2); int* cur2P = (int*)gp(g_cur2);
    int* cnt3P = (int*)gp(g_cnt3); int* cur3P = (int*)gp(g_cur3);
    int* m1P = (int*)gp(g_m1); int* m2P = (int*)gp(g_m2); int* m3P = (int*)gp(g_m3);
    int* map1P = (int*)gp(g_map1); int* map2P = (int*)gp(g_map2); int* map3P = (int*)gp(g_map3);
    int* p1P = (int*)gp(g_perm1); int* p2P = (int*)gp(g_perm2); int* p3P = (int*)gp(g_perm3);
    int* bsumP = (int*)gp(g_bsum);
    float* h0P = (float*)gp(g_h0);
    float* h1P = (float*)gp(g_h1);
    float* h2P = (float*)gp(g_h2);
    float* h3P = (float*)gp(g_h3);
    float* xaP = (float*)gp(g_xa);
    float* xbP = (float*)gp(g_xb);
    float* aggP = (float*)gp(g_agg);
    float* scoreP = (float*)gp(g_score);
    u64* keysP = (u64*)gp(g_keys);
    float* atfP = (float*)gp(g_atf);
    float* w0tfP = (float*)gp(g_w0tf);
    float* wctfP = (float*)gp(g_wctf);

    const int EG = cdiv(NE, 256);

    auto scan = [&](const int* in, int* outp, int n) {
        int nb = cdiv(n, 4096);
        k_scan_block<<<nb, 1024>>>(in, bsumP, n);
        k_scan_down<<<nb, 1024>>>(in, bsumP, outp, n);
    };

    // tensor conv: agg + asplit + 3xTF32 mma gemm (relu always on)
    auto tconv = [&](const float* xin, int n, const int* rp, const int* esrc,
                     const float* gB, int planeB, const float* bias,
                     float* outb, int Ka) {
        if (Ka == CH)
            k_aggmax256<<<cdiv(n, 8), 256>>>(rp, esrc, xin, aggP, n);
        else
            k_aggmax32<<<cdiv(n, 8), 256>>>(rp, esrc, xin, aggP, n);
        int K2 = 2 * Ka;
        int sh = (K2 == 512) ? 9 : 6;
        k_asplit<<<cdiv(n * K2 / 4, 256), 256>>>(aggP, xin, atfP, n, Ka, sh);
        dim3 g(cdiv(n, 128), 2);
        k_mgemm<<<g, 256, MG_SMEM>>>(atfP, gB, bias, outb, n, K2, planeB);
    };

    auto pool = [&](const float* xin, int n, int P, int k, const float* w,
                    int* perm, int* map, float* xout) {
        k_scorekey<<<cdiv(P * 32, 256), 256>>>(xin, w, scoreP, keysP, n, P);
        k_bit_full8<<<P / 8192, 1024, 65536>>>(keysP);
        for (int kk = 16384; kk <= P; kk <<= 1) {
            int j = kk >> 1;
            while (j >= 8192) {
                if (j >= 16384) {
                    k_bit_glob2<<<P / 4 / 256, 256>>>(keysP, j, kk);
                    j >>= 2;
                } else {
                    k_bit_glob<<<P / 256, 256>>>(keysP, j, kk);
                    j >>= 1;
                }
            }
            k_bit_smem8<<<P / 8192, 1024, 65536>>>(keysP, kk);
        }
        k_build<<<cdiv(k * 32, 256), 256>>>(keysP, xin, scoreP, xout, perm, map, k);
    };

    // init + weight split + edge decode + level-0 CSR
    k_zeroall<<<cdiv(N0, 256), 256>>>(eidx);
    k_wsplit<<<cdiv(16384 + 5 * 131072, 256), 256>>>(w0l, w0r, dwl, dwr, uwl, uwr);
    k_convert<<<EG, 256>>>(eidx);
    scan(cnt0P, rp0P, N0);
    k_scatter<<<EG, 256>>>(srcP, dstP, nullptr, NE, rp0P, cur0P, es0P);

    // level-0 conv (Ka=32)
    tconv(x_in, N0, rp0P, es0P, w0tfP, 16384, b0, h0P, CIN);

    // --- pool 1 + conv 1 ---
    pool(h0P, N0, PW1, KP1, poolw, p1P, map1P, xaP);
    k_relabel<<<EG, 256>>>(srcP, dstP, nullptr, NE, map1P, e1sP, e1dP, m1P, cnt1P);
    scan(cnt1P, rp1P, KP1);
    k_scatter<<<EG, 256>>>(e1sP, e1dP, m1P, 0, rp1P, cur1P, es1P);
    tconv(xaP, KP1, rp1P, es1P, wctfP + 0 * 262144, 131072, db, h1P, CH);

    // --- pool 2 + conv 2 ---
    pool(h1P, KP1, PW2, KP2, poolw + CH, p2P, map2P, xaP);
    k_relabel<<<EG, 256>>>(e1sP, e1dP, m1P, 0, map2P, e2sP, e2dP, m2P, cnt2P);
    scan(cnt2P, rp2P, KP2);
    k_scatter<<<EG, 256>>>(e2sP, e2dP, m2P, 0, rp2P, cur2P, es2P);
    tconv(xaP, KP2, rp2P, es2P, wctfP + 1 * 262144, 131072, db + CH, h2P, CH);

    // --- pool 3 + conv 3 ---
    pool(h2P, KP2, PW3, KP3, poolw + 2 * CH, p3P, map3P, xaP);
    k_relabel<<<EG, 256>>>(e2sP, e2dP, m2P, 0, map3P, e3sP, e3dP, m3P, cnt3P);
    scan(cnt3P, rp3P, KP3);
    k_scatter<<<EG, 256>>>(e3sP, e3dP, m3P, 0, rp3P, cur3P, es3P);
    tconv(xaP, KP3, rp3P, es3P, wctfP + 2 * 262144, 131072, db + 2 * CH, h3P, CH);

    // --- up path ---
    k_unpool<<<cdiv(KP2 * 64, 256), 256>>>(h2P, h3P, map3P, xaP, KP2);
    tconv(xaP, KP2, rp2P, es2P, wctfP + 3 * 262144, 131072, ub, xbP, CH);

    k_unpool<<<cdiv(KP1 * 64, 256), 256>>>(h1P, xbP, map2P, xaP, KP1);
    tconv(xaP, KP1, rp1P, es1P, wctfP + 4 * 262144, 131072, ub + CH, xbP, CH);

    k_unpool<<<cdiv(N0 * 64, 256), 256>>>(h0P, xbP, map1P, xaP, N0);
    k_aggmax256<<<cdiv(N0, 8), 256>>>(rp0P, es0P, xaP, aggP, N0);
    k_final<<<cdiv(N0, 256), 256>>>(aggP, xaP, uwlL, uwrL, ubL, out, N0);
}

// round 10
// speedup vs baseline: 1.1106x; 1.0223x over previous
#include <cuda_runtime.h>
#include <cuda_bf16.h>
#include <math.h>
#include <stdint.h>

#define N0   50000
#define KP1  25000
#define KP2  12500
#define KP3  6250
#define NE   800000
#define CH   256
#define CIN  32
#define PW1  65536
#define PW2  32768
#define PW3  16384

typedef unsigned long long u64;

// ------------------------- scratch (device globals) -------------------------
__device__ int   g_src[NE], g_dst[NE];
__device__ int   g_e1s[NE], g_e1d[NE], g_e2s[NE], g_e2d[NE], g_e3s[NE], g_e3d[NE];
__device__ int   g_es0[NE], g_es1[NE], g_es2[NE], g_es3[NE];
__device__ int   g_rp0[N0+1], g_rp1[KP1+1], g_rp2[KP2+1], g_rp3[KP3+1];
__device__ int   g_cnt0[N0], g_cur0[N0];
__device__ int   g_cnt1[KP1], g_cur1[KP1];
__device__ int   g_cnt2[KP2], g_cur2[KP2];
__device__ int   g_cnt3[KP3], g_cur3[KP3];
__device__ int   g_m1, g_m2, g_m3, g_flag;
__device__ int   g_map1[N0], g_map2[KP1], g_map3[KP2];
__device__ int   g_perm1[KP1], g_perm2[KP2], g_perm3[KP3];
__device__ int   g_bsum[64];
__device__ __align__(128) float g_h0[N0*CH];
__device__ __align__(128) float g_h1[KP1*CH];
__device__ __align__(128) float g_h2[KP2*CH];
__device__ __align__(128) float g_h3[KP3*CH];
__device__ __align__(128) float g_xa[N0*CH];
__device__ __align__(128) float g_xb[KP1*CH];
__device__ __align__(128) float g_agg[N0*CH];
__device__ float g_score[N0];
__device__ u64   g_keys[PW1];
// bf16-split weight planes (persistent per replay)
__device__ __align__(128) __nv_bfloat16 g_w0bf[3 * 256 * 64];       // conv0 B planes
__device__ __align__(128) __nv_bfloat16 g_wcbf[5 * 3 * 256 * 512];  // 5 big-conv B planes

// ------------------------- helpers ------------------------------------------
__device__ __forceinline__ float4 max4(float4 a, float4 b) {
    return make_float4(fmaxf(a.x, b.x), fmaxf(a.y, b.y),
                       fmaxf(a.z, b.z), fmaxf(a.w, b.w));
}

__device__ __forceinline__ void bsplit(float v, unsigned short& b0,
                                       unsigned short& b1, unsigned short& b2) {
    __nv_bfloat16 h0 = __float2bfloat16(v);
    float r1 = v - __bfloat162float(h0);
    __nv_bfloat16 h1 = __float2bfloat16(r1);
    float r2 = r1 - __bfloat162float(h1);
    __nv_bfloat16 h2 = __float2bfloat16(r2);
    b0 = __bfloat16_as_ushort(h0);
    b1 = __bfloat16_as_ushort(h1);
    b2 = __bfloat16_as_ushort(h2);
}

#define MMA_BF16(d, a, b)                                                  \
    asm volatile(                                                          \
        "mma.sync.aligned.m16n8k16.row.col.f32.bf16.bf16.f32 "             \
        "{%0,%1,%2,%3}, {%4,%5,%6,%7}, {%8,%9}, {%0,%1,%2,%3};"            \
        : "+f"((d)[0]), "+f"((d)[1]), "+f"((d)[2]), "+f"((d)[3])           \
        : "r"((a)[0]), "r"((a)[1]), "r"((a)[2]), "r"((a)[3]),              \
          "r"((b)[0]), "r"((b)[1]))

// ------------------------- init + int64/int32 detect -------------------------
__global__ void k_zeroall(const unsigned* __restrict__ w) {
    int i = blockIdx.x * blockDim.x + threadIdx.x;
    if (i < N0)  { g_cnt0[i] = 0; g_cur0[i] = 0; g_map1[i] = -1; }
    if (i < KP1) { g_cnt1[i] = 0; g_cur1[i] = 0; g_map2[i] = -1; }
    if (i < KP2) { g_cnt2[i] = 0; g_cur2[i] = 0; g_map3[i] = -1; }
    if (i < KP3) { g_cnt3[i] = 0; g_cur3[i] = 0; }
    if (i == 0) { g_m1 = 0; g_m2 = 0; g_m3 = 0; }
    if (blockIdx.x == 0) {
        __shared__ int any;
        if (threadIdx.x == 0) any = 0;
        __syncthreads();
        for (int t = threadIdx.x; t < 2048; t += blockDim.x)
            if (w[2*t + 1] != 0u) any = 1;
        __syncthreads();
        if (threadIdx.x == 0) g_flag = (any == 0) ? 1 : 0;
    }
}

// ------------------------- weight split to bf16 planes -----------------------
__global__ void k_wsplit(const float* __restrict__ w0l, const float* __restrict__ w0r,
                         const float* __restrict__ dwl, const float* __restrict__ dwr,
                         const float* __restrict__ uwl, const float* __restrict__ uwr) {
    int i = blockIdx.x * blockDim.x + threadIdx.x;
    if (i < 16384) {  // conv0: B[n(256)][k(64)], k<32 -> w0l[k][n], else w0r
        int nn = i >> 6, k = i & 63;
        float v = (k < 32) ? w0l[k * 256 + nn] : w0r[(k - 32) * 256 + nn];
        unsigned short b0, b1, b2;
        bsplit(v, b0, b1, b2);
        g_w0bf[i]         = __ushort_as_bfloat16(b0);
        g_w0bf[16384 + i] = __ushort_as_bfloat16(b1);
        g_w0bf[32768 + i] = __ushort_as_bfloat16(b2);
        return;
    }
    int t = i - 16384;
    if (t >= 5 * 131072) return;
    int c = t / 131072;            // conv 0..4 (down0..2, up0..1)
    int r = t - c * 131072;
    int nn = r >> 9, k = r & 511;
    float v;
    if (k < 256) v = (c < 3) ? dwl[c * 65536 + k * 256 + nn]
                             : uwl[(c - 3) * 65536 + k * 256 + nn];
    else {
        int kk = k - 256;
        v = (c < 3) ? dwr[c * 65536 + kk * 256 + nn]
                    : uwr[(c - 3) * 65536 + kk * 256 + nn];
    }
    unsigned short b0, b1, b2;
    bsplit(v, b0, b1, b2);
    size_t base = (size_t)c * 393216 + r;
    g_wcbf[base]          = __ushort_as_bfloat16(b0);
    g_wcbf[base + 131072] = __ushort_as_bfloat16(b1);
    g_wcbf[base + 262144] = __ushort_as_bfloat16(b2);
}

// ------------------------- edge decode + level-0 dst count -------------------
__global__ void k_convert(const unsigned* __restrict__ w) {
    int i = blockIdx.x * blockDim.x + threadIdx.x;
    if (i >= NE) return;
    int s, d;
    if (g_flag) {
        s = (int)w[2*i];
        d = (int)w[2*(NE + i)];
    } else {
        const int* p = (const int*)w;
        s = p[i];
        d = p[NE + i];
    }
    g_src[i] = s;
    g_dst[i] = d;
    atomicAdd(&g_cnt0[d], 1);
}

// ------------------------- parallel exclusive scan ---------------------------
__global__ void k_scan_block(const int* __restrict__ in, int* bsum, int n) {
    __shared__ int sh[1024];
    int t = threadIdx.x;
    int base = blockIdx.x * 4096 + t * 4;
    int s = 0;
#pragma unroll
    for (int q = 0; q < 4; q++) {
        int idx = base + q;
        s += (idx < n) ? in[idx] : 0;
    }
    sh[t] = s;
    __syncthreads();
    for (int o = 512; o > 0; o >>= 1) {
        if (t < o) sh[t] += sh[t + o];
        __syncthreads();
    }
    if (t == 0) bsum[blockIdx.x] = sh[0];
}

__global__ void k_scan_down(const int* __restrict__ in, const int* __restrict__ bsum,
                            int* out, int n) {
    __shared__ int sh[1024];
    __shared__ int base0;
    int t = threadIdx.x;
    if (t < 32) {
        int nb = gridDim.x;
        int v = (t < nb) ? bsum[t] : 0;
#pragma unroll
        for (int o = 1; o < 32; o <<= 1) {
            int u = __shfl_up_sync(0xffffffffu, v, o);
            if (t >= o) v += u;
        }
        if (t == 0) base0 = 0;
        __syncwarp();
        if ((int)t == (int)blockIdx.x - 1) base0 = v;
    }
    int base = blockIdx.x * 4096 + t * 4;
    int v4[4];
    int s = 0;
#pragma unroll
    for (int q = 0; q < 4; q++) {
        int idx = base + q;
        v4[q] = (idx < n) ? in[idx] : 0;
        s += v4[q];
    }
    sh[t] = s;
    __syncthreads();
    for (int o = 1; o < 1024; o <<= 1) {
        int u = (t >= o) ? sh[t - o] : 0;
        __syncthreads();
        sh[t] += u;
        __syncthreads();
    }
    int pref = base0 + sh[t] - s;
#pragma unroll
    for (int q = 0; q < 4; q++) {
        int idx = base + q;
        if (idx < n) out[idx] = pref;
        if (idx == n - 1) out[n] = pref + v4[q];
        pref += v4[q];
    }
}

__global__ void k_scatter(const int* __restrict__ s, const int* __restrict__ d,
                          const int* mptr, int fixedM,
                          const int* __restrict__ rp, int* cur, int* esrc) {
    int m = mptr ? *mptr : fixedM;
    int i = blockIdx.x * blockDim.x + threadIdx.x;
    if (i >= m) return;
    int dd = d[i];
    int pos = rp[dd] + atomicAdd(&cur[dd], 1);
    esrc[pos] = s[i];
}

__global__ void k_relabel(const int* __restrict__ ps, const int* __restrict__ pd,
                          const int* mptr, int fixedM,
                          const int* __restrict__ map,
                          int* os, int* od, int* om, int* cnt) {
    int m = mptr ? *mptr : fixedM;
    int i = blockIdx.x * blockDim.x + threadIdx.x;
    if (i >= m) return;
    int a = map[ps[i]], b = map[pd[i]];
    if (a >= 0 && b >= 0) {
        int p = atomicAdd(om, 1);
        os[p] = a; od[p] = b;
        atomicAdd(&cnt[b], 1);
    }
}

// ------------------------- max aggregation (CSR) -----------------------------
__global__ void k_aggmax32(const int* __restrict__ rp, const int* __restrict__ es,
                           const float* __restrict__ x, float* agg, int n) {
    int warp = (blockIdx.x * blockDim.x + threadIdx.x) >> 5;
    int lane = threadIdx.x & 31;
    if (warp >= n) return;
    int s = rp[warp], e = rp[warp + 1];
    float m = -INFINITY;
    int t = s;
    for (; t + 4 <= e; t += 4) {
        float v0 = x[(size_t)es[t] * CIN + lane];
        float v1 = x[(size_t)es[t+1] * CIN + lane];
        float v2 = x[(size_t)es[t+2] * CIN + lane];
        float v3 = x[(size_t)es[t+3] * CIN + lane];
        m = fmaxf(m, fmaxf(fmaxf(v0, v1), fmaxf(v2, v3)));
    }
    for (; t < e; t++)
        m = fmaxf(m, x[(size_t)es[t] * CIN + lane]);
    agg[(size_t)warp * CIN + lane] = (e > s) ? m : 0.0f;
}

__global__ void k_aggmax256(const int* __restrict__ rp, const int* __restrict__ es,
                            const float* __restrict__ x, float* agg, int n) {
    int warp = (blockIdx.x * blockDim.x + threadIdx.x) >> 5;
    int lane = threadIdx.x & 31;
    if (warp >= n) return;
    int s = rp[warp], e = rp[warp + 1];
    const float ninf = -INFINITY;
    float4 m0 = make_float4(ninf, ninf, ninf, ninf);
    float4 m1 = m0;
    int t = s;
    for (; t + 2 <= e; t += 2) {
        const float4* p0 = (const float4*)(x + (size_t)es[t] * CH) + lane * 2;
        const float4* p1 = (const float4*)(x + (size_t)es[t+1] * CH) + lane * 2;
        float4 a0 = p0[0], a1 = p0[1];
        float4 b0 = p1[0], b1 = p1[1];
        m0 = max4(m0, a0); m1 = max4(m1, a1);
        m0 = max4(m0, b0); m1 = max4(m1, b1);
    }
    if (t < e) {
        const float4* p0 = (const float4*)(x + (size_t)es[t] * CH) + lane * 2;
        m0 = max4(m0, p0[0]); m1 = max4(m1, p0[1]);
    }
    float4 z = make_float4(0.f, 0.f, 0.f, 0.f);
    bool has = (e > s);
    float4* ar = (float4*)(agg + (size_t)warp * CH) + lane * 2;
    ar[0] = has ? m0 : z;
    ar[1] = has ? m1 : z;
}

// ------------------------- bf16x6 tensor GEMM (mma.sync m16n8k16) ------------
// C[n,256] = relu( [agg|xin][n,2Ka] @ B(256,2Ka)^T + bias )
// A split to 3 bf16 planes IN-KERNEL; B pre-split (gB: 3 planes, row-major [n][k]).
// Block 128x128 (grid.y=2), 8 warps (4m x 2n), warp tile 32x64, BK=32.
// smem rows stride 40 bf16 (20 words) -> conflict-free fragment LDS.
#define ROWW  20                      // words per smem row (32 bf16 + 8 pad)
#define PLW   (128 * ROWW)            // words per plane (2560)
#define MB_SMEM (2 * 3 * PLW * 4)     // A(3 planes) + B(3 planes) = 61440 B

static __device__ __constant__ int c_pa[6] = {0, 0, 1, 1, 0, 2};
static __device__ __constant__ int c_pb[6] = {0, 1, 0, 1, 2, 0};

__global__ void __launch_bounds__(256)
k_mgemm(const float* __restrict__ agg, const float* __restrict__ xin,
        const __nv_bfloat16* __restrict__ gB, const float* __restrict__ bias,
        float* __restrict__ C, int n, int Ka, int planeB) {
    extern __shared__ unsigned smw[];
    unsigned* sA = smw;                 // [3][128][ROWW]
    unsigned* sB = smw + 3 * PLW;
    const int tid = threadIdx.x;
    const int wid = tid >> 5, lane = tid & 31;
    const int wm = wid & 3, wn = wid >> 2;
    const int g = lane >> 2, t4 = lane & 3;
    const int bm = blockIdx.x * 128, bn = blockIdx.y * 128;
    const int Ktot = 2 * Ka;
    const int nc = Ktot >> 5;

    float acc[2][8][4];
#pragma unroll
    for (int mt = 0; mt < 2; mt++)
#pragma unroll
        for (int nt = 0; nt < 8; nt++)
#pragma unroll
            for (int q = 0; q < 4; q++) acc[mt][nt][q] = 0.f;

    const int lr = tid >> 1;            // 0..127
    const int half = tid & 1;
    const int arow = bm + lr;
    const bool aok = arow < n;

    for (int c = 0; c < nc; c++) {
        // ---- load A: fp32 -> split -> 3 bf16 planes in smem ----
#pragma unroll
        for (int i = 0; i < 4; i++) {
            int k0 = half * 16 + i * 4;
            int gk = c * 32 + k0;
            float4 v = make_float4(0.f, 0.f, 0.f, 0.f);
            if (aok) {
                const float* sp = (gk < Ka) ? (agg + (size_t)arow * Ka + gk)
                                            : (xin + (size_t)arow * Ka + (gk - Ka));
                v = *(const float4*)sp;
            }
            unsigned short p0[4], p1[4], p2[4];
            bsplit(v.x, p0[0], p1[0], p2[0]);
            bsplit(v.y, p0[1], p1[1], p2[1]);
            bsplit(v.z, p0[2], p1[2], p2[2]);
            bsplit(v.w, p0[3], p1[3], p2[3]);
            int w = lr * ROWW + (k0 >> 1);
            sA[w]               = (unsigned)p0[0] | ((unsigned)p0[1] << 16);
            sA[w + 1]           = (unsigned)p0[2] | ((unsigned)p0[3] << 16);
            sA[PLW + w]         = (unsigned)p1[0] | ((unsigned)p1[1] << 16);
            sA[PLW + w + 1]     = (unsigned)p1[2] | ((unsigned)p1[3] << 16);
            sA[2 * PLW + w]     = (unsigned)p2[0] | ((unsigned)p2[1] << 16);
            sA[2 * PLW + w + 1] = (unsigned)p2[2] | ((unsigned)p2[3] << 16);
        }
        // ---- load B: bf16 planes from global ----
#pragma unroll
        for (int p = 0; p < 3; p++) {
            const __nv_bfloat16* bp = gB + (size_t)p * planeB +
                                      (size_t)(bn + lr) * Ktot + c * 32 + half * 16;
            uint4 u0 = *(const uint4*)bp;
            uint4 u1 = *(const uint4*)(bp + 8);
            uint4* dst = (uint4*)(sB + p * PLW + lr * ROWW + half * 8);
            dst[0] = u0;
            dst[1] = u1;
        }
        __syncthreads();

        // ---- 2 k16 steps ----
#pragma unroll
        for (int s = 0; s < 2; s++) {
            unsigned a[3][2][4];
#pragma unroll
            for (int p = 0; p < 3; p++) {
                const unsigned* pa = sA + p * PLW;
#pragma unroll
                for (int mt = 0; mt < 2; mt++) {
                    int m0 = wm * 32 + mt * 16;
                    a[p][mt][0] = pa[(m0 + g) * ROWW + s * 8 + t4];
                    a[p][mt][1] = pa[(m0 + g + 8) * ROWW + s * 8 + t4];
                    a[p][mt][2] = pa[(m0 + g) * ROWW + s * 8 + t4 + 4];
                    a[p][mt][3] = pa[(m0 + g + 8) * ROWW + s * 8 + t4 + 4];
                }
            }
#pragma unroll
            for (int pr = 0; pr < 6; pr++) {
                const int pa = c_pa[pr], pb = c_pb[pr];
                const unsigned* pbb = sB + pb * PLW;
#pragma unroll
                for (int nt = 0; nt < 8; nt++) {
                    int n0 = wn * 64 + nt * 8;
                    unsigned b[2];
                    b[0] = pbb[(n0 + g) * ROWW + s * 8 + t4];
                    b[1] = pbb[(n0 + g) * ROWW + s * 8 + t4 + 4];
                    MMA_BF16(acc[0][nt], a[pa][0], b);
                    MMA_BF16(acc[1][nt], a[pa][1], b);
                }
            }
        }
        __syncthreads();
    }

    // ---- epilogue: bias + relu, float2 stores ----
#pragma unroll
    for (int mt = 0; mt < 2; mt++) {
        int r0 = bm + wm * 32 + mt * 16 + g;
#pragma unroll
        for (int nt = 0; nt < 8; nt++) {
            int col = bn + wn * 64 + nt * 8 + t4 * 2;
            float bb0 = bias[col], bb1 = bias[col + 1];
            if (r0 < n) {
                float2 v;
                v.x = fmaxf(acc[mt][nt][0] + bb0, 0.f);
                v.y = fmaxf(acc[mt][nt][1] + bb1, 0.f);
                *(float2*)(C + (size_t)r0 * CH + col) = v;
            }
            if (r0 + 8 < n) {
                float2 v;
                v.x = fmaxf(acc[mt][nt][2] + bb0, 0.f);
                v.y = fmaxf(acc[mt][nt][3] + bb1, 0.f);
                *(float2*)(C + (size_t)(r0 + 8) * CH + col) = v;
            }
        }
    }
}

// ------------------------- TopK pooling --------------------------------------
__global__ void k_scorekey(const float* __restrict__ x, const float* __restrict__ w,
                           float* score, u64* keys, int n, int P) {
    int gw = (blockIdx.x * blockDim.x + threadIdx.x) >> 5;
    int lane = threadIdx.x & 31;
    if (gw >= P) return;
    if (gw >= n) {
        if (lane == 0) keys[gw] = 0xFFFFFFFFFFFFFFFFull;
        return;
    }
    float p = 0.f, w2 = 0.f;
    const float* xr = x + (size_t)gw * CH;
    for (int c = lane; c < CH; c += 32) {
        float wv = w[c];
        p += xr[c] * wv;
        w2 += wv * wv;
    }
#pragma unroll
    for (int o = 16; o > 0; o >>= 1) {
        p  += __shfl_xor_sync(0xffffffffu, p, o);
        w2 += __shfl_xor_sync(0xffffffffu, w2, o);
    }
    if (lane == 0) {
        float s = tanhf(p / sqrtf(w2));
        score[gw] = s;
        unsigned u = __float_as_uint(s);
        unsigned mono = (u & 0x80000000u) ? ~u : (u | 0x80000000u);
        keys[gw] = ((u64)(~mono) << 32) | (unsigned)gw;
    }
}

__global__ void k_bit_full8(u64* keys) {
    extern __shared__ u64 s[];
    int base = blockIdx.x * 8192;
    int t = threadIdx.x;
#pragma unroll
    for (int i = 0; i < 8; i++) s[t + i * 1024] = keys[base + t + i * 1024];
    __syncthreads();
    for (int k = 2; k <= 8192; k <<= 1) {
        for (int j = k >> 1; j > 0; j >>= 1) {
#pragma unroll
            for (int q = 0; q < 4; q++) {
                int p = t + q * 1024;
                int li = ((p & ~(j - 1)) << 1) | (p & (j - 1));
                bool up = (((base + li) & k) == 0);
                u64 a = s[li], b = s[li + j];
                if ((a > b) == up) { s[li] = b; s[li + j] = a; }
            }
            __syncthreads();
        }
    }
#pragma unroll
    for (int i = 0; i < 8; i++) keys[base + t + i * 1024] = s[t + i * 1024];
}

__global__ void k_bit_smem8(u64* keys, int k) {
    extern __shared__ u64 s[];
    int base = blockIdx.x * 8192;
    int t = threadIdx.x;
#pragma unroll
    for (int i = 0; i < 8; i++) s[t + i * 1024] = keys[base + t + i * 1024];
    __syncthreads();
    for (int j = 4096; j > 0; j >>= 1) {
#pragma unroll
        for (int q = 0; q < 4; q++) {
            int p = t + q * 1024;
            int li = ((p & ~(j - 1)) << 1) | (p & (j - 1));
            bool up = (((base + li) & k) == 0);
            u64 a = s[li], b = s[li + j];
            if ((a > b) == up) { s[li] = b; s[li + j] = a; }
        }
        __syncthreads();
    }
#pragma unroll
    for (int i = 0; i < 8; i++) keys[base + t + i * 1024] = s[t + i * 1024];
}

__global__ void k_bit_glob(u64* keys, int j, int k) {
    int i = blockIdx.x * blockDim.x + threadIdx.x;
    int ixj = i ^ j;
    if (ixj > i) {
        bool up = ((i & k) == 0);
        u64 a = keys[i], b = keys[ixj];
        if ((a > b) == up) { keys[i] = b; keys[ixj] = a; }
    }
}

__global__ void k_bit_glob2(u64* keys, int j, int k) {
    int t = blockIdx.x * blockDim.x + threadIdx.x;
    int j2 = j >> 1;
    int b = ((t & ~(j2 - 1)) << 1) | (t & (j2 - 1));
    b = ((b & ~(j - 1)) << 1) | (b & (j - 1));
    u64 v0 = keys[b], v1 = keys[b + j2], v2 = keys[b + j], v3 = keys[b + j + j2];
    bool up = ((b & k) == 0);
    u64 tmp;
    if ((v0 > v2) == up) { tmp = v0; v0 = v2; v2 = tmp; }
    if ((v1 > v3) == up) { tmp = v1; v1 = v3; v3 = tmp; }
    if ((v0 > v1) == up) { tmp = v0; v0 = v1; v1 = tmp; }
    if ((v2 > v3) == up) { tmp = v2; v2 = v3; v3 = tmp; }
    keys[b] = v0; keys[b + j2] = v1; keys[b + j] = v2; keys[b + j + j2] = v3;
}

__global__ void k_build(const u64* __restrict__ keys, const float* __restrict__ xin,
                        const float* __restrict__ score, float* xout,
                        int* perm, int* map, int k) {
    int gw = (blockIdx.x * blockDim.x + threadIdx.x) >> 5;
    int lane = threadIdx.x & 31;
    if (gw >= k) return;
    int idx = (int)(keys[gw] & 0xFFFFFFFFull);
    if (lane == 0) { perm[gw] = idx; map[idx] = gw; }
    float v = score[idx];
    const float4* xr = (const float4*)(xin + (size_t)idx * CH);
    float4* xo = (float4*)(xout + (size_t)gw * CH);
#pragma unroll
    for (int c = lane; c < 64; c += 32) {
        float4 a = xr[c];
        xo[c] = make_float4(a.x * v, a.y * v, a.z * v, a.w * v);
    }
}

// ------------------------- unpool --------------------------------------------
__global__ void k_unpool(const float* __restrict__ h, const float* __restrict__ deep,
                         const int* __restrict__ map, float* __restrict__ xa, int n) {
    int i = blockIdx.x * blockDim.x + threadIdx.x;
    if (i >= n * 64) return;
    int r = i >> 6, c4 = i & 63;
    float4 v = ((const float4*)h)[i];
    int g = map[r];
    if (g >= 0) {
        float4 d = ((const float4*)deep)[g * 64 + c4];
        v.x += d.x; v.y += d.y; v.z += d.z; v.w += d.w;
    }
    ((float4*)xa)[i] = v;
}

// ------------------------- final conv (M=3) + tanh*0.5 -----------------------
__global__ void k_final(const float* __restrict__ agg, const float* __restrict__ x,
                        const float* __restrict__ wl, const float* __restrict__ wr,
                        const float* __restrict__ b, float* out, int n) {
    __shared__ float swl[CH * 3], swr[CH * 3], sb[3];
    for (int i = threadIdx.x; i < CH * 3; i += blockDim.x) {
        swl[i] = wl[i];
        swr[i] = wr[i];
    }
    if (threadIdx.x < 3) sb[threadIdx.x] = b[threadIdx.x];
    __syncthreads();
    int node = blockIdx.x * blockDim.x + threadIdx.x;
    if (node >= n) return;
    float a0 = sb[0], a1 = sb[1], a2 = sb[2];
    const float4* ar = (const float4*)(agg + (size_t)node * CH);
    const float4* xr = (const float4*)(x + (size_t)node * CH);
#pragma unroll 2
    for (int c4 = 0; c4 < 64; c4++) {
        float4 av = ar[c4], xv = xr[c4];
        int c = c4 * 4;
        a0 += av.x * swl[c * 3 + 0] + xv.x * swr[c * 3 + 0];
        a1 += av.x * swl[c * 3 + 1] + xv.x * swr[c * 3 + 1];
        a2 += av.x * swl[c * 3 + 2] + xv.x * swr[c * 3 + 2];
        a0 += av.y * swl[c * 3 + 3] + xv.y * swr[c * 3 + 3];
        a1 += av.y * swl[c * 3 + 4] + xv.y * swr[c * 3 + 4];
        a2 += av.y * swl[c * 3 + 5] + xv.y * swr[c * 3 + 5];
        a0 += av.z * swl[c * 3 + 6] + xv.z * swr[c * 3 + 6];
        a1 += av.z * swl[c * 3 + 7] + xv.z * swr[c * 3 + 7];
        a2 += av.z * swl[c * 3 + 8] + xv.z * swr[c * 3 + 8];
        a0 += av.w * swl[c * 3 + 9] + xv.w * swr[c * 3 + 9];
        a1 += av.w * swl[c * 3 + 10] + xv.w * swr[c * 3 + 10];
        a2 += av.w * swl[c * 3 + 11] + xv.w * swr[c * 3 + 11];
    }
    out[node * 3 + 0] = tanhf(a0) * 0.5f;
    out[node * 3 + 1] = tanhf(a1) * 0.5f;
    out[node * 3 + 2] = tanhf(a2) * 0.5f;
}

// ------------------------- host orchestration --------------------------------
static inline int cdiv(int a, int b) { return (a + b - 1) / b; }

template <class T>
static void* gp(const T& sym) {
    void* p = nullptr;
    cudaGetSymbolAddress(&p, sym);
    return p;
}

extern "C" void kernel_launch(void* const* d_in, const int* in_sizes, int n_in,
                              void* d_out, int out_size) {
    const float* x_in = (const float*)d_in[0];
    const unsigned* eidx = (const unsigned*)d_in[1];
    const float* w0l  = (const float*)d_in[2];
    const float* w0r  = (const float*)d_in[3];
    const float* b0   = (const float*)d_in[4];
    const float* dwl  = (const float*)d_in[5];
    const float* dwr  = (const float*)d_in[6];
    const float* db   = (const float*)d_in[7];
    const float* poolw = (const float*)d_in[8];
    const float* uwl  = (const float*)d_in[9];
    const float* uwr  = (const float*)d_in[10];
    const float* ub   = (const float*)d_in[11];
    const float* uwlL = (const float*)d_in[12];
    const float* uwrL = (const float*)d_in[13];
    const float* ubL  = (const float*)d_in[14];
    float* out = (float*)d_out;

    static bool attr_done = false;
    if (!attr_done) {
        cudaFuncSetAttribute(k_bit_full8, cudaFuncAttributeMaxDynamicSharedMemorySize, 65536);
        cudaFuncSetAttribute(k_bit_smem8, cudaFuncAttributeMaxDynamicSharedMemorySize, 65536);
        cudaFuncSetAttribute(k_mgemm, cudaFuncAttributeMaxDynamicSharedMemorySize, MB_SMEM);
        attr_done = true;
    }

    int* srcP = (int*)gp(g_src);
    int* dstP = (int*)gp(g_dst);
    int* e1sP = (int*)gp(g_e1s); int* e1dP = (int*)gp(g_e1d);
    int* e2sP = (int*)gp(g_e2s); int* e2dP = (int*)gp(g_e2d);
    int* e3sP = (int*)gp(g_e3s); int* e3dP = (int*)gp(g_e3d);
    int* es0P = (int*)gp(g_es0); int* es1P = (int*)gp(g_es1);
    int* es2P = (int*)gp(g_es2); int* es3P = (int*)gp(g_es3);
    int* rp0P = (int*)gp(g_rp0); int* rp1P = (int*)gp(g_rp1);
    int* rp2P = (int*)gp(g_rp2); int* rp3P = (int*)gp(g_rp3);
    int* cnt0P = (int*)gp(g_cnt0); int* cur0P = (int*)gp(g_cur0);
    int* cnt1P = (int*)gp(g_cnt1); int* cur1P = (int*)gp(g_cur1);
    int* cnt2P = (int*)gp(g_cnt2); int* cur2P = (int*)gp(g_cur2);
    int* cnt3P = (int*)gp(g_cnt3); int* cur3P = (int*)gp(g_cur3);
    int* m1P = (int*)gp(g_m1); int* m2P = (int*)gp(g_m2); int* m3P = (int*)gp(g_m3);
    int* map1P = (int*)gp(g_map1); int* map2P = (int*)gp(g_map2); int* map3P = (int*)gp(g_map3);
    int* p1P = (int*)gp(g_perm1); int* p2P = (int*)gp(g_perm2); int* p3P = (int*)gp(g_perm3);
    int* bsumP = (int*)gp(g_bsum);
    float* h0P = (float*)gp(g_h0);
    float* h1P = (float*)gp(g_h1);
    float* h2P = (float*)gp(g_h2);
    float* h3P = (float*)gp(g_h3);
    float* xaP = (float*)gp(g_xa);
    float* xbP = (float*)gp(g_xb);
    float* aggP = (float*)gp(g_agg);
    float* scoreP = (float*)gp(g_score);
    u64* keysP = (u64*)gp(g_keys);
    __nv_bfloat16* w0bfP = (__nv_bfloat16*)gp(g_w0bf);
    __nv_bfloat16* wcbfP = (__nv_bfloat16*)gp(g_wcbf);

    const int EG = cdiv(NE, 256);

    auto scan = [&](const int* in, int* outp, int n) {
        int nb = cdiv(n, 4096);
        k_scan_block<<<nb, 1024>>>(in, bsumP, n);
        k_scan_down<<<nb, 1024>>>(in, bsumP, outp, n);
    };

    // tensor conv: agg + bf16x6 mma gemm with fused A split (relu on)
    auto tconv = [&](const float* xin, int n, const int* rp, const int* esrc,
                     const __nv_bfloat16* gB, int planeB, const float* bias,
                     float* outb, int Ka) {
        if (Ka == CH)
            k_aggmax256<<<cdiv(n, 8), 256>>>(rp, esrc, xin, aggP, n);
        else
            k_aggmax32<<<cdiv(n, 8), 256>>>(rp, esrc, xin, aggP, n);
        dim3 g(cdiv(n, 128), 2);
        k_mgemm<<<g, 256, MB_SMEM>>>(aggP, xin, gB, bias, outb, n, Ka, planeB);
    };

    auto pool = [&](const float* xin, int n, int P, int k, const float* w,
                    int* perm, int* map, float* xout) {
        k_scorekey<<<cdiv(P * 32, 256), 256>>>(xin, w, scoreP, keysP, n, P);
        k_bit_full8<<<P / 8192, 1024, 65536>>>(keysP);
        for (int kk = 16384; kk <= P; kk <<= 1) {
            int j = kk >> 1;
            while (j >= 8192) {
                if (j >= 16384) {
                    k_bit_glob2<<<P / 4 / 256, 256>>>(keysP, j, kk);
                    j >>= 2;
                } else {
                    k_bit_glob<<<P / 256, 256>>>(keysP, j, kk);
                    j >>= 1;
                }
            }
            k_bit_smem8<<<P / 8192, 1024, 65536>>>(keysP, kk);
        }
        k_build<<<cdiv(k * 32, 256), 256>>>(keysP, xin, scoreP, xout, perm, map, k);
    };

    // init + weight split + edge decode + level-0 CSR
    k_zeroall<<<cdiv(N0, 256), 256>>>(eidx);
    k_wsplit<<<cdiv(16384 + 5 * 131072, 256), 256>>>(w0l, w0r, dwl, dwr, uwl, uwr);
    k_convert<<<EG, 256>>>(eidx);
    scan(cnt0P, rp0P, N0);
    k_scatter<<<EG, 256>>>(srcP, dstP, nullptr, NE, rp0P, cur0P, es0P);

    // level-0 conv (Ka=32)
    tconv(x_in, N0, rp0P, es0P, w0bfP, 16384, b0, h0P, CIN);

    // --- pool 1 + conv 1 ---
    pool(h0P, N0, PW1, KP1, poolw, p1P, map1P, xaP);
    k_relabel<<<EG, 256>>>(srcP, dstP, nullptr, NE, map1P, e1sP, e1dP, m1P, cnt1P);
    scan(cnt1P, rp1P, KP1);
    k_scatter<<<EG, 256>>>(e1sP, e1dP, m1P, 0, rp1P, cur1P, es1P);
    tconv(xaP, KP1, rp1P, es1P, wcbfP + 0 * 393216, 131072, db, h1P, CH);

    // --- pool 2 + conv 2 ---
    pool(h1P, KP1, PW2, KP2, poolw + CH, p2P, map2P, xaP);
    k_relabel<<<EG, 256>>>(e1sP, e1dP, m1P, 0, map2P, e2sP, e2dP, m2P, cnt2P);
    scan(cnt2P, rp2P, KP2);
    k_scatter<<<EG, 256>>>(e2sP, e2dP, m2P, 0, rp2P, cur2P, es2P);
    tconv(xaP, KP2, rp2P, es2P, wcbfP + 1 * 393216, 131072, db + CH, h2P, CH);

    // --- pool 3 + conv 3 ---
    pool(h2P, KP2, PW3, KP3, poolw + 2 * CH, p3P, map3P, xaP);
    k_relabel<<<EG, 256>>>(e2sP, e2dP, m2P, 0, map3P, e3sP, e3dP, m3P, cnt3P);
    scan(cnt3P, rp3P, KP3);
    k_scatter<<<EG, 256>>>(e3sP, e3dP, m3P, 0, rp3P, cur3P, es3P);
    tconv(xaP, KP3, rp3P, es3P, wcbfP + 2 * 393216, 131072, db + 2 * CH, h3P, CH);

    // --- up path ---
    k_unpool<<<cdiv(KP2 * 64, 256), 256>>>(h2P, h3P, map3P, xaP, KP2);
    tconv(xaP, KP2, rp2P, es2P, wcbfP + 3 * 393216, 131072, ub, xbP, CH);

    k_unpool<<<cdiv(KP1 * 64, 256), 256>>>(h1P, xbP, map2P, xaP, KP1);
    tconv(xaP, KP1, rp1P, es1P, wcbfP + 4 * 393216, 131072, ub + CH, xbP, CH);

    k_unpool<<<cdiv(N0 * 64, 256), 256>>>(h0P, xbP, map1P, xaP, N0);
    k_aggmax256<<<cdiv(N0, 8), 256>>>(rp0P, es0P, xaP, aggP, N0);
    k_final<<<cdiv(N0, 256), 256>>>(aggP, xaP, uwlL, uwrL, ubL, out, N0);
}

// round 11
// speedup vs baseline: 1.2019x; 1.0823x over previous
#include <cuda_runtime.h>
#include <math.h>
#include <stdint.h>

#define N0   50000
#define KP1  25000
#define KP2  12500
#define KP3  6250
#define NE   800000
#define CH   256
#define CIN  32
#define PW1  65536
#define PW2  32768
#define PW3  16384

typedef unsigned long long u64;

// ------------------------- scratch (device globals) -------------------------
__device__ int   g_src[NE], g_dst[NE];
__device__ int   g_e1s[NE], g_e1d[NE], g_e2s[NE], g_e2d[NE], g_e3s[NE], g_e3d[NE];
__device__ int   g_es0[NE], g_es1[NE], g_es2[NE], g_es3[NE];
__device__ int   g_rp0[N0+1], g_rp1[KP1+1], g_rp2[KP2+1], g_rp3[KP3+1];
__device__ int   g_cnt0[N0], g_cur0[N0];
__device__ int   g_cnt1[KP1], g_cur1[KP1];
__device__ int   g_cnt2[KP2], g_cur2[KP2];
__device__ int   g_cnt3[KP3], g_cur3[KP3];
__device__ int   g_m1, g_m2, g_m3, g_flag;
__device__ int   g_map1[N0], g_map2[KP1], g_map3[KP2];
__device__ int   g_perm1[KP1], g_perm2[KP2], g_perm3[KP3];
__device__ int   g_bsum[64];
__device__ __align__(128) float g_h0[N0*CH];
__device__ __align__(128) float g_h1[KP1*CH];
__device__ __align__(128) float g_h2[KP2*CH];
__device__ __align__(128) float g_h3[KP3*CH];
__device__ __align__(128) float g_xa[N0*CH];
__device__ __align__(128) float g_xb[KP1*CH];
__device__ __align__(128) float g_agg[N0*CH];
__device__ float g_score[N0];
__device__ u64   g_keys[PW1];

// ------------------------- fp32x2 helpers ------------------------------------
__device__ __forceinline__ u64 splat2(float f) {
    u64 r;
    unsigned u = __float_as_uint(f);
    asm("mov.b64 %0, {%1, %1};" : "=l"(r) : "r"(u));
    return r;
}
__device__ __forceinline__ void fma2(u64& d, u64 a, u64 b) {
    asm("fma.rn.f32x2 %0, %1, %2, %0;" : "+l"(d) : "l"(a), "l"(b));
}
__device__ __forceinline__ void unpack2(u64 v, float& lo, float& hi) {
    unsigned a, b;
    asm("mov.b64 {%0, %1}, %2;" : "=r"(a), "=r"(b) : "l"(v));
    lo = __uint_as_float(a);
    hi = __uint_as_float(b);
}
__device__ __forceinline__ float4 max4(float4 a, float4 b) {
    return make_float4(fmaxf(a.x, b.x), fmaxf(a.y, b.y),
                       fmaxf(a.z, b.z), fmaxf(a.w, b.w));
}

// ------------------------- init + int64/int32 detect (one launch) ------------
__global__ void k_zeroall(const unsigned* __restrict__ w) {
    int i = blockIdx.x * blockDim.x + threadIdx.x;
    if (i < N0)  { g_cnt0[i] = 0; g_cur0[i] = 0; g_map1[i] = -1; }
    if (i < KP1) { g_cnt1[i] = 0; g_cur1[i] = 0; g_map2[i] = -1; }
    if (i < KP2) { g_cnt2[i] = 0; g_cur2[i] = 0; g_map3[i] = -1; }
    if (i < KP3) { g_cnt3[i] = 0; g_cur3[i] = 0; }
    if (i == 0) { g_m1 = 0; g_m2 = 0; g_m3 = 0; }
    if (blockIdx.x == 0) {
        __shared__ int any;
        if (threadIdx.x == 0) any = 0;
        __syncthreads();
        for (int t = threadIdx.x; t < 2048; t += blockDim.x)
            if (w[2*t + 1] != 0u) any = 1;
        __syncthreads();
        if (threadIdx.x == 0) g_flag = (any == 0) ? 1 : 0;
    }
}

// ------------------------- edge decode + level-0 dst count -------------------
__global__ void k_convert(const unsigned* __restrict__ w) {
    int i = blockIdx.x * blockDim.x + threadIdx.x;
    if (i >= NE) return;
    int s, d;
    if (g_flag) {
        s = (int)w[2*i];
        d = (int)w[2*(NE + i)];
    } else {
        const int* p = (const int*)w;
        s = p[i];
        d = p[NE + i];
    }
    g_src[i] = s;
    g_dst[i] = d;
    atomicAdd(&g_cnt0[d], 1);
}

// ------------------------- parallel exclusive scan ---------------------------
__global__ void k_scan_block(const int* __restrict__ in, int* bsum, int n) {
    __shared__ int sh[1024];
    int t = threadIdx.x;
    int base = blockIdx.x * 4096 + t * 4;
    int s = 0;
#pragma unroll
    for (int q = 0; q < 4; q++) {
        int idx = base + q;
        s += (idx < n) ? in[idx] : 0;
    }
    sh[t] = s;
    __syncthreads();
    for (int o = 512; o > 0; o >>= 1) {
        if (t < o) sh[t] += sh[t + o];
        __syncthreads();
    }
    if (t == 0) bsum[blockIdx.x] = sh[0];
}

__global__ void k_scan_down(const int* __restrict__ in, const int* __restrict__ bsum,
                            int* out, int n) {
    __shared__ int sh[1024];
    __shared__ int base0;
    int t = threadIdx.x;
    if (t < 32) {
        int nb = gridDim.x;
        int v = (t < nb) ? bsum[t] : 0;
#pragma unroll
        for (int o = 1; o < 32; o <<= 1) {
            int u = __shfl_up_sync(0xffffffffu, v, o);
            if (t >= o) v += u;
        }
        if (t == 0) base0 = 0;
        __syncwarp();
        if ((int)t == (int)blockIdx.x - 1) base0 = v;
    }
    int base = blockIdx.x * 4096 + t * 4;
    int v4[4];
    int s = 0;
#pragma unroll
    for (int q = 0; q < 4; q++) {
        int idx = base + q;
        v4[q] = (idx < n) ? in[idx] : 0;
        s += v4[q];
    }
    sh[t] = s;
    __syncthreads();
    for (int o = 1; o < 1024; o <<= 1) {
        int u = (t >= o) ? sh[t - o] : 0;
        __syncthreads();
        sh[t] += u;
        __syncthreads();
    }
    int pref = base0 + sh[t] - s;
#pragma unroll
    for (int q = 0; q < 4; q++) {
        int idx = base + q;
        if (idx < n) out[idx] = pref;
        if (idx == n - 1) out[n] = pref + v4[q];
        pref += v4[q];
    }
}

__global__ void k_scatter(const int* __restrict__ s, const int* __restrict__ d,
                          const int* mptr, int fixedM,
                          const int* __restrict__ rp, int* cur, int* esrc) {
    int m = mptr ? *mptr : fixedM;
    int i = blockIdx.x * blockDim.x + threadIdx.x;
    if (i >= m) return;
    int dd = d[i];
    int pos = rp[dd] + atomicAdd(&cur[dd], 1);
    esrc[pos] = s[i];
}

// relabel edges + count dst degrees in one pass
__global__ void k_relabel(const int* __restrict__ ps, const int* __restrict__ pd,
                          const int* mptr, int fixedM,
                          const int* __restrict__ map,
                          int* os, int* od, int* om, int* cnt) {
    int m = mptr ? *mptr : fixedM;
    int i = blockIdx.x * blockDim.x + threadIdx.x;
    if (i >= m) return;
    int a = map[ps[i]], b = map[pd[i]];
    if (a >= 0 && b >= 0) {
        int p = atomicAdd(om, 1);
        os[p] = a; od[p] = b;
        atomicAdd(&cnt[b], 1);
    }
}

// ------------------------- max aggregation (CSR, vectorized) -----------------
__global__ void k_aggmax32(const int* __restrict__ rp, const int* __restrict__ es,
                           const float* __restrict__ x, float* agg, int n) {
    int warp = (blockIdx.x * blockDim.x + threadIdx.x) >> 5;
    int lane = threadIdx.x & 31;
    if (warp >= n) return;
    int s = rp[warp], e = rp[warp + 1];
    float m = -INFINITY;
    int t = s;
    for (; t + 4 <= e; t += 4) {
        float v0 = x[(size_t)es[t] * CIN + lane];
        float v1 = x[(size_t)es[t+1] * CIN + lane];
        float v2 = x[(size_t)es[t+2] * CIN + lane];
        float v3 = x[(size_t)es[t+3] * CIN + lane];
        m = fmaxf(m, fmaxf(fmaxf(v0, v1), fmaxf(v2, v3)));
    }
    for (; t < e; t++)
        m = fmaxf(m, x[(size_t)es[t] * CIN + lane]);
    agg[(size_t)warp * CIN + lane] = (e > s) ? m : 0.0f;
}

__global__ void k_aggmax256(const int* __restrict__ rp, const int* __restrict__ es,
                            const float* __restrict__ x, float* agg, int n) {
    int warp = (blockIdx.x * blockDim.x + threadIdx.x) >> 5;
    int lane = threadIdx.x & 31;
    if (warp >= n) return;
    int s = rp[warp], e = rp[warp + 1];
    const float ninf = -INFINITY;
    float4 m0 = make_float4(ninf, ninf, ninf, ninf);
    float4 m1 = m0;
    int t = s;
    for (; t + 2 <= e; t += 2) {
        const float4* p0 = (const float4*)(x + (size_t)es[t] * CH) + lane * 2;
        const float4* p1 = (const float4*)(x + (size_t)es[t+1] * CH) + lane * 2;
        float4 a0 = p0[0], a1 = p0[1];
        float4 b0 = p1[0], b1 = p1[1];
        m0 = max4(m0, a0); m1 = max4(m1, a1);
        m0 = max4(m0, b0); m1 = max4(m1, b1);
    }
    if (t < e) {
        const float4* p0 = (const float4*)(x + (size_t)es[t] * CH) + lane * 2;
        m0 = max4(m0, p0[0]); m1 = max4(m1, p0[1]);
    }
    float4 z = make_float4(0.f, 0.f, 0.f, 0.f);
    bool has = (e > s);
    float4* ar = (float4*)(agg + (size_t)warp * CH) + lane * 2;
    ar[0] = has ? m0 : z;
    ar[1] = has ? m1 : z;
}

// ------------------------- fused dual GEMM (FFMA2, BM=128, double-buffered) --
__global__ void __launch_bounds__(256, 2)
k_gemm2(const float* __restrict__ A0, const float* __restrict__ A1, int Ka,
        const float* __restrict__ B0, const float* __restrict__ B1,
        const float* __restrict__ bias, float* __restrict__ C,
        int n, int relu) {
    __shared__ __align__(16) float As[2][16][128];
    __shared__ __align__(16) float Bs[2][16][128];
    const int bm = blockIdx.x * 128, bn = blockIdx.y * 128;
    const int tid = threadIdx.x;
    const int tx = tid & 15, ty = tid >> 4;
    const int m0 = ty * 8, c0 = tx * 8;

    u64 acc[4][8];
#pragma unroll
    for (int i = 0; i < 4; i++)
#pragma unroll
        for (int j = 0; j < 8; j++) acc[i][j] = 0ull;

    const int aRow = tid >> 1;
    const int aK   = (tid & 1) * 8;
    const int bRow = tid >> 4;
    const int bCol = (tid & 15) * 8;
    const int Ktot = 2 * Ka;
    const int nk = Ktot / 16;

    float4 av0, av1, bv0, bv1;

    // prologue: load tile 0
    {
        const float* A = A0;
        const float* B = B0;
        av0 = make_float4(0.f, 0.f, 0.f, 0.f); av1 = av0;
        if (bm + aRow < n) {
            const float* ap = A + (size_t)(bm + aRow) * Ka + aK;
            av0 = *(const float4*)ap;
            av1 = *(const float4*)(ap + 4);
        }
        const float* bp = B + (size_t)bRow * CH + bn + bCol;
        bv0 = *(const float4*)bp;
        bv1 = *(const float4*)(bp + 4);
        As[0][aK + 0][aRow] = av0.x; As[0][aK + 1][aRow] = av0.y;
        As[0][aK + 2][aRow] = av0.z; As[0][aK + 3][aRow] = av0.w;
        As[0][aK + 4][aRow] = av1.x; As[0][aK + 5][aRow] = av1.y;
        As[0][aK + 6][aRow] = av1.z; As[0][aK + 7][aRow] = av1.w;
        *(float4*)(&Bs[0][bRow][bCol])     = bv0;
        *(float4*)(&Bs[0][bRow][bCol + 4]) = bv1;
    }
    __syncthreads();

    for (int it = 0; it < nk; it++) {
        const int buf = it & 1;
        const bool more = (it + 1 < nk);
        if (more) {
            int k0 = (it + 1) * 16;
            const int h = (k0 >= Ka);
            const int kl = k0 - (h ? Ka : 0);
            const float* A = h ? A1 : A0;
            const float* B = h ? B1 : B0;
            av0 = make_float4(0.f, 0.f, 0.f, 0.f); av1 = av0;
            if (bm + aRow < n) {
                const float* ap = A + (size_t)(bm + aRow) * Ka + kl + aK;
                av0 = *(const float4*)ap;
                av1 = *(const float4*)(ap + 4);
            }
            const float* bp = B + (size_t)(kl + bRow) * CH + bn + bCol;
            bv0 = *(const float4*)bp;
            bv1 = *(const float4*)(bp + 4);
        }

#pragma unroll
        for (int kk = 0; kk < 16; kk++) {
            const u64* ap64 = (const u64*)(&As[buf][kk][m0]);
            u64 a0 = ap64[0], a1 = ap64[1], a2 = ap64[2], a3 = ap64[3];
            float4 bx = *(const float4*)(&Bs[buf][kk][c0]);
            float4 by = *(const float4*)(&Bs[buf][kk][c0 + 4]);
            u64 b0s = splat2(bx.x), b1s = splat2(bx.y);
            u64 b2s = splat2(bx.z), b3s = splat2(bx.w);
            u64 b4s = splat2(by.x), b5s = splat2(by.y);
            u64 b6s = splat2(by.z), b7s = splat2(by.w);
            fma2(acc[0][0], a0, b0s); fma2(acc[0][1], a0, b1s);
            fma2(acc[0][2], a0, b2s); fma2(acc[0][3], a0, b3s);
            fma2(acc[0][4], a0, b4s); fma2(acc[0][5], a0, b5s);
            fma2(acc[0][6], a0, b6s); fma2(acc[0][7], a0, b7s);
            fma2(acc[1][0], a1, b0s); fma2(acc[1][1], a1, b1s);
            fma2(acc[1][2], a1, b2s); fma2(acc[1][3], a1, b3s);
            fma2(acc[1][4], a1, b4s); fma2(acc[1][5], a1, b5s);
            fma2(acc[1][6], a1, b6s); fma2(acc[1][7], a1, b7s);
            fma2(acc[2][0], a2, b0s); fma2(acc[2][1], a2, b1s);
            fma2(acc[2][2], a2, b2s); fma2(acc[2][3], a2, b3s);
            fma2(acc[2][4], a2, b4s); fma2(acc[2][5], a2, b5s);
            fma2(acc[2][6], a2, b6s); fma2(acc[2][7], a2, b7s);
            fma2(acc[3][0], a3, b0s); fma2(acc[3][1], a3, b1s);
            fma2(acc[3][2], a3, b2s); fma2(acc[3][3], a3, b3s);
            fma2(acc[3][4], a3, b4s); fma2(acc[3][5], a3, b5s);
            fma2(acc[3][6], a3, b6s); fma2(acc[3][7], a3, b7s);
        }

        if (more) {
            const int nb = buf ^ 1;
            As[nb][aK + 0][aRow] = av0.x; As[nb][aK + 1][aRow] = av0.y;
            As[nb][aK + 2][aRow] = av0.z; As[nb][aK + 3][aRow] = av0.w;
            As[nb][aK + 4][aRow] = av1.x; As[nb][aK + 5][aRow] = av1.y;
            As[nb][aK + 6][aRow] = av1.z; As[nb][aK + 7][aRow] = av1.w;
            *(float4*)(&Bs[nb][bRow][bCol])     = bv0;
            *(float4*)(&Bs[nb][bRow][bCol + 4]) = bv1;
        }
        __syncthreads();
    }

    float bv[8];
#pragma unroll
    for (int j = 0; j < 8; j++) bv[j] = bias[bn + c0 + j];

#pragma unroll
    for (int i2 = 0; i2 < 4; i2++) {
        int r0 = bm + m0 + 2 * i2;
        float v0[8], v1[8];
#pragma unroll
        for (int j = 0; j < 8; j++) {
            float lo, hi;
            unpack2(acc[i2][j], lo, hi);
            v0[j] = lo + bv[j];
            v1[j] = hi + bv[j];
            if (relu) { v0[j] = fmaxf(v0[j], 0.f); v1[j] = fmaxf(v1[j], 0.f); }
        }
        if (r0 < n) {
            float* cp = C + (size_t)r0 * CH + bn + c0;
            *(float4*)cp       = make_float4(v0[0], v0[1], v0[2], v0[3]);
            *(float4*)(cp + 4) = make_float4(v0[4], v0[5], v0[6], v0[7]);
        }
        if (r0 + 1 < n) {
            float* cp = C + (size_t)(r0 + 1) * CH + bn + c0;
            *(float4*)cp       = make_float4(v1[0], v1[1], v1[2], v1[3]);
            *(float4*)(cp + 4) = make_float4(v1[4], v1[5], v1[6], v1[7]);
        }
    }
}

// ------------------------- TopK pooling --------------------------------------
__global__ void k_scorekey(const float* __restrict__ x, const float* __restrict__ w,
                           float* score, u64* keys, int n, int P) {
    int gw = (blockIdx.x * blockDim.x + threadIdx.x) >> 5;
    int lane = threadIdx.x & 31;
    if (gw >= P) return;
    if (gw >= n) {
        if (lane == 0) keys[gw] = 0xFFFFFFFFFFFFFFFFull;
        return;
    }
    float p = 0.f, w2 = 0.f;
    const float* xr = x + (size_t)gw * CH;
    for (int c = lane; c < CH; c += 32) {
        float wv = w[c];
        p += xr[c] * wv;
        w2 += wv * wv;
    }
#pragma unroll
    for (int o = 16; o > 0; o >>= 1) {
        p  += __shfl_xor_sync(0xffffffffu, p, o);
        w2 += __shfl_xor_sync(0xffffffffu, w2, o);
    }
    if (lane == 0) {
        float s = tanhf(p / sqrtf(w2));
        score[gw] = s;
        unsigned u = __float_as_uint(s);
        unsigned mono = (u & 0x80000000u) ? ~u : (u | 0x80000000u);
        keys[gw] = ((u64)(~mono) << 32) | (unsigned)gw;
    }
}

// chunk = 8192 elements, 1024 threads, 64KB dynamic smem
__global__ void k_bit_full8(u64* keys) {
    extern __shared__ u64 s[];
    int base = blockIdx.x * 8192;
    int t = threadIdx.x;
#pragma unroll
    for (int i = 0; i < 8; i++) s[t + i * 1024] = keys[base + t + i * 1024];
    __syncthreads();
    for (int k = 2; k <= 8192; k <<= 1) {
        for (int j = k >> 1; j > 0; j >>= 1) {
#pragma unroll
            for (int q = 0; q < 4; q++) {
                int p = t + q * 1024;
                int li = ((p & ~(j - 1)) << 1) | (p & (j - 1));
                bool up = (((base + li) & k) == 0);
                u64 a = s[li], b = s[li + j];
                if ((a > b) == up) { s[li] = b; s[li + j] = a; }
            }
            __syncthreads();
        }
    }
#pragma unroll
    for (int i = 0; i < 8; i++) keys[base + t + i * 1024] = s[t + i * 1024];
}

__global__ void k_bit_smem8(u64* keys, int k) {  // j = 4096..1 for given k
    extern __shared__ u64 s[];
    int base = blockIdx.x * 8192;
    int t = threadIdx.x;
#pragma unroll
    for (int i = 0; i < 8; i++) s[t + i * 1024] = keys[base + t + i * 1024];
    __syncthreads();
    for (int j = 4096; j > 0; j >>= 1) {
#pragma unroll
        for (int q = 0; q < 4; q++) {
            int p = t + q * 1024;
            int li = ((p & ~(j - 1)) << 1) | (p & (j - 1));
            bool up = (((base + li) & k) == 0);
            u64 a = s[li], b = s[li + j];
            if ((a > b) == up) { s[li] = b; s[li + j] = a; }
        }
        __syncthreads();
    }
#pragma unroll
    for (int i = 0; i < 8; i++) keys[base + t + i * 1024] = s[t + i * 1024];
}

__global__ void k_bit_glob(u64* keys, int j, int k) {
    int i = blockIdx.x * blockDim.x + threadIdx.x;
    int ixj = i ^ j;
    if (ixj > i) {
        bool up = ((i & k) == 0);
        u64 a = keys[i], b = keys[ixj];
        if ((a > b) == up) { keys[i] = b; keys[ixj] = a; }
    }
}

// fused two global strides (j and j/2); P/4 threads
__global__ void k_bit_glob2(u64* keys, int j, int k) {
    int t = blockIdx.x * blockDim.x + threadIdx.x;
    int j2 = j >> 1;
    int b = ((t & ~(j2 - 1)) << 1) | (t & (j2 - 1));
    b = ((b & ~(j - 1)) << 1) | (b & (j - 1));
    u64 v0 = keys[b], v1 = keys[b + j2], v2 = keys[b + j], v3 = keys[b + j + j2];
    bool up = ((b & k) == 0);
    u64 tmp;
    if ((v0 > v2) == up) { tmp = v0; v0 = v2; v2 = tmp; }
    if ((v1 > v3) == up) { tmp = v1; v1 = v3; v3 = tmp; }
    if ((v0 > v1) == up) { tmp = v0; v0 = v1; v1 = tmp; }
    if ((v2 > v3) == up) { tmp = v2; v2 = v3; v3 = tmp; }
    keys[b] = v0; keys[b + j2] = v1; keys[b + j] = v2; keys[b + j + j2] = v3;
}

__global__ void k_build(const u64* __restrict__ keys, const float* __restrict__ xin,
                        const float* __restrict__ score, float* xout,
                        int* perm, int* map, int k) {
    int gw = (blockIdx.x * blockDim.x + threadIdx.x) >> 5;
    int lane = threadIdx.x & 31;
    if (gw >= k) return;
    int idx = (int)(keys[gw] & 0xFFFFFFFFull);
    if (lane == 0) { perm[gw] = idx; map[idx] = gw; }
    float v = score[idx];
    const float4* xr = (const float4*)(xin + (size_t)idx * CH);
    float4* xo = (float4*)(xout + (size_t)gw * CH);
#pragma unroll
    for (int c = lane; c < 64; c += 32) {
        float4 a = xr[c];
        xo[c] = make_float4(a.x * v, a.y * v, a.z * v, a.w * v);
    }
}

// ------------------------- unpool: xa = h + gather(deep via map) -------------
__global__ void k_unpool(const float* __restrict__ h, const float* __restrict__ deep,
                         const int* __restrict__ map, float* __restrict__ xa, int n) {
    int i = blockIdx.x * blockDim.x + threadIdx.x;
    if (i >= n * 64) return;
    int r = i >> 6, c4 = i & 63;
    float4 v = ((const float4*)h)[i];
    int g = map[r];
    if (g >= 0) {
        float4 d = ((const float4*)deep)[g * 64 + c4];
        v.x += d.x; v.y += d.y; v.z += d.z; v.w += d.w;
    }
    ((float4*)xa)[i] = v;
}

// ------------------------- final conv (M=3) + tanh*0.5 -----------------------
__global__ void k_final(const float* __restrict__ agg, const float* __restrict__ x,
                        const float* __restrict__ wl, const float* __restrict__ wr,
                        const float* __restrict__ b, float* out, int n) {
    __shared__ float swl[CH * 3], swr[CH * 3], sb[3];
    for (int i = threadIdx.x; i < CH * 3; i += blockDim.x) {
        swl[i] = wl[i];
        swr[i] = wr[i];
    }
    if (threadIdx.x < 3) sb[threadIdx.x] = b[threadIdx.x];
    __syncthreads();
    int node = blockIdx.x * blockDim.x + threadIdx.x;
    if (node >= n) return;
    float a0 = sb[0], a1 = sb[1], a2 = sb[2];
    const float4* ar = (const float4*)(agg + (size_t)node * CH);
    const float4* xr = (const float4*)(x + (size_t)node * CH);
#pragma unroll 2
    for (int c4 = 0; c4 < 64; c4++) {
        float4 av = ar[c4], xv = xr[c4];
        int c = c4 * 4;
        a0 += av.x * swl[c * 3 + 0] + xv.x * swr[c * 3 + 0];
        a1 += av.x * swl[c * 3 + 1] + xv.x * swr[c * 3 + 1];
        a2 += av.x * swl[c * 3 + 2] + xv.x * swr[c * 3 + 2];
        a0 += av.y * swl[c * 3 + 3] + xv.y * swr[c * 3 + 3];
        a1 += av.y * swl[c * 3 + 4] + xv.y * swr[c * 3 + 4];
        a2 += av.y * swl[c * 3 + 5] + xv.y * swr[c * 3 + 5];
        a0 += av.z * swl[c * 3 + 6] + xv.z * swr[c * 3 + 6];
        a1 += av.z * swl[c * 3 + 7] + xv.z * swr[c * 3 + 7];
        a2 += av.z * swl[c * 3 + 8] + xv.z * swr[c * 3 + 8];
        a0 += av.w * swl[c * 3 + 9] + xv.w * swr[c * 3 + 9];
        a1 += av.w * swl[c * 3 + 10] + xv.w * swr[c * 3 + 10];
        a2 += av.w * swl[c * 3 + 11] + xv.w * swr[c * 3 + 11];
    }
    out[node * 3 + 0] = tanhf(a0) * 0.5f;
    out[node * 3 + 1] = tanhf(a1) * 0.5f;
    out[node * 3 + 2] = tanhf(a2) * 0.5f;
}

// ------------------------- host orchestration --------------------------------
static inline int cdiv(int a, int b) { return (a + b - 1) / b; }

template <class T>
static void* gp(const T& sym) {
    void* p = nullptr;
    cudaGetSymbolAddress(&p, sym);
    return p;
}

extern "C" void kernel_launch(void* const* d_in, const int* in_sizes, int n_in,
                              void* d_out, int out_size) {
    const float* x_in = (const float*)d_in[0];
    const unsigned* eidx = (const unsigned*)d_in[1];
    const float* w0l  = (const float*)d_in[2];
    const float* w0r  = (const float*)d_in[3];
    const float* b0   = (const float*)d_in[4];
    const float* dwl  = (const float*)d_in[5];
    const float* dwr  = (const float*)d_in[6];
    const float* db   = (const float*)d_in[7];
    const float* poolw = (const float*)d_in[8];
    const float* uwl  = (const float*)d_in[9];
    const float* uwr  = (const float*)d_in[10];
    const float* ub   = (const float*)d_in[11];
    const float* uwlL = (const float*)d_in[12];
    const float* uwrL = (const float*)d_in[13];
    const float* ubL  = (const float*)d_in[14];
    float* out = (float*)d_out;

    static bool attr_done = false;
    if (!attr_done) {
        cudaFuncSetAttribute(k_bit_full8, cudaFuncAttributeMaxDynamicSharedMemorySize, 65536);
        cudaFuncSetAttribute(k_bit_smem8, cudaFuncAttributeMaxDynamicSharedMemorySize, 65536);
        attr_done = true;
    }

    int* srcP = (int*)gp(g_src);
    int* dstP = (int*)gp(g_dst);
    int* e1sP = (int*)gp(g_e1s); int* e1dP = (int*)gp(g_e1d);
    int* e2sP = (int*)gp(g_e2s); int* e2dP = (int*)gp(g_e2d);
    int* e3sP = (int*)gp(g_e3s); int* e3dP = (int*)gp(g_e3d);
    int* es0P = (int*)gp(g_es0); int* es1P = (int*)gp(g_es1);
    int* es2P = (int*)gp(g_es2); int* es3P = (int*)gp(g_es3);
    int* rp0P = (int*)gp(g_rp0); int* rp1P = (int*)gp(g_rp1);
    int* rp2P = (int*)gp(g_rp2); int* rp3P = (int*)gp(g_rp3);
    int* cnt0P = (int*)gp(g_cnt0); int* cur0P = (int*)gp(g_cur0);
    int* cnt1P = (int*)gp(g_cnt1); int* cur1P = (int*)gp(g_cur1);
    int* cnt2P = (int*)gp(g_cnt2); int* cur2P = (int*)gp(g_cur2);
    int* cnt3P = (int*)gp(g_cnt3); int* cur3P = (int*)gp(g_cur3);
    int* m1P = (int*)gp(g_m1); int* m2P = (int*)gp(g_m2); int* m3P = (int*)gp(g_m3);
    int* map1P = (int*)gp(g_map1); int* map2P = (int*)gp(g_map2); int* map3P = (int*)gp(g_map3);
    int* p1P = (int*)gp(g_perm1); int* p2P = (int*)gp(g_perm2); int* p3P = (int*)gp(g_perm3);
    int* bsumP = (int*)gp(g_bsum);
    float* h0P = (float*)gp(g_h0);
    float* h1P = (float*)gp(g_h1);
    float* h2P = (float*)gp(g_h2);
    float* h3P = (float*)gp(g_h3);
    float* xaP = (float*)gp(g_xa);
    float* xbP = (float*)gp(g_xb);
    float* aggP = (float*)gp(g_agg);
    float* scoreP = (float*)gp(g_score);
    u64* keysP = (u64*)gp(g_keys);

    const int EG = cdiv(NE, 256);

    auto scan = [&](const int* in, int* outp, int n) {
        int nb = cdiv(n, 4096);
        k_scan_block<<<nb, 1024>>>(in, bsumP, n);
        k_scan_down<<<nb, 1024>>>(in, bsumP, outp, n);
    };

    auto conv = [&](const float* xin, int n, const int* rp, const int* esrc,
                    const float* wl, const float* wr, const float* bias,
                    float* outb, int relu) {
        k_aggmax256<<<cdiv(n, 8), 256>>>(rp, esrc, xin, aggP, n);
        dim3 g(cdiv(n, 128), 2);
        k_gemm2<<<g, 256>>>(aggP, xin, CH, wl, wr, bias, outb, n, relu);
    };

    auto pool = [&](const float* xin, int n, int P, int k, const float* w,
                    int* perm, int* map, float* xout) {
        k_scorekey<<<cdiv(P * 32, 256), 256>>>(xin, w, scoreP, keysP, n, P);
        k_bit_full8<<<P / 8192, 1024, 65536>>>(keysP);
        for (int kk = 16384; kk <= P; kk <<= 1) {
            int j = kk >> 1;
            while (j >= 8192) {
                if (j >= 16384) {
                    k_bit_glob2<<<P / 4 / 256, 256>>>(keysP, j, kk);
                    j >>= 2;
                } else {
                    k_bit_glob<<<P / 256, 256>>>(keysP, j, kk);
                    j >>= 1;
                }
            }
            k_bit_smem8<<<P / 8192, 1024, 65536>>>(keysP, kk);
        }
        k_build<<<cdiv(k * 32, 256), 256>>>(keysP, xin, scoreP, xout, perm, map, k);
    };

    // init + decode + level-0 CSR
    k_zeroall<<<cdiv(N0, 256), 256>>>(eidx);
    k_convert<<<EG, 256>>>(eidx);
    scan(cnt0P, rp0P, N0);
    k_scatter<<<EG, 256>>>(srcP, dstP, nullptr, NE, rp0P, cur0P, es0P);

    // level-0 conv (C_IN=32)
    k_aggmax32<<<cdiv(N0, 8), 256>>>(rp0P, es0P, x_in, aggP, N0);
    {
        dim3 g(cdiv(N0, 128), 2);
        k_gemm2<<<g, 256>>>(aggP, x_in, CIN, w0l, w0r, b0, h0P, N0, 1);
    }

    // --- pool 1 + conv 1 ---
    pool(h0P, N0, PW1, KP1, poolw, p1P, map1P, xaP);
    k_relabel<<<EG, 256>>>(srcP, dstP, nullptr, NE, map1P, e1sP, e1dP, m1P, cnt1P);
    scan(cnt1P, rp1P, KP1);
    k_scatter<<<EG, 256>>>(e1sP, e1dP, m1P, 0, rp1P, cur1P, es1P);
    conv(xaP, KP1, rp1P, es1P, dwl, dwr, db, h1P, 1);

    // --- pool 2 + conv 2 ---
    pool(h1P, KP1, PW2, KP2, poolw + CH, p2P, map2P, xaP);
    k_relabel<<<EG, 256>>>(e1sP, e1dP, m1P, 0, map2P, e2sP, e2dP, m2P, cnt2P);
    scan(cnt2P, rp2P, KP2);
    k_scatter<<<EG, 256>>>(e2sP, e2dP, m2P, 0, rp2P, cur2P, es2P);
    conv(xaP, KP2, rp2P, es2P, dwl + CH*CH, dwr + CH*CH, db + CH, h2P, 1);

    // --- pool 3 + conv 3 ---
    pool(h2P, KP2, PW3, KP3, poolw + 2*CH, p3P, map3P, xaP);
    k_relabel<<<EG, 256>>>(e2sP, e2dP, m2P, 0, map3P, e3sP, e3dP, m3P, cnt3P);
    scan(cnt3P, rp3P, KP3);
    k_scatter<<<EG, 256>>>(e3sP, e3dP, m3P, 0, rp3P, cur3P, es3P);
    conv(xaP, KP3, rp3P, es3P, dwl + 2*CH*CH, dwr + 2*CH*CH, db + 2*CH, h3P, 1);

    // --- up path (gather-based unpool) ---
    k_unpool<<<cdiv(KP2 * 64, 256), 256>>>(h2P, h3P, map3P, xaP, KP2);
    conv(xaP, KP2, rp2P, es2P, uwl, uwr, ub, xbP, 1);

    k_unpool<<<cdiv(KP1 * 64, 256), 256>>>(h1P, xbP, map2P, xaP, KP1);
    conv(xaP, KP1, rp1P, es1P, uwl + CH*CH, uwr + CH*CH, ub + CH, xbP, 1);

    k_unpool<<<cdiv(N0 * 64, 256), 256>>>(h0P, xbP, map1P, xaP, N0);
    k_aggmax256<<<cdiv(N0, 8), 256>>>(rp0P, es0P, xaP, aggP, N0);
    k_final<<<cdiv(N0, 256), 256>>>(aggP, xaP, uwlL, uwrL, ubL, out, N0);
}